// round 14
// baseline (speedup 1.0000x reference)
#include <cuda_runtime.h>
#include <cuda_bf16.h>
#include <cstddef>
#include <cstdint>

#define B_    8
#define C_    192
#define H_    128
#define W_    128
#define HW_   16384
#define HEADS 4
#define DH    48
#define PLANE (C_ * C_)
#define NCHUNK 32

// ---------------- scratch ----------------------------------------------------
#define TEN    ((size_t)B_ * C_ * HW_)
#define BFTEN  (TEN / 2)
#define OFF_QB   ((size_t)0)
#define OFF_KB   (BFTEN * 1)
#define OFF_VB   (BFTEN * 2)
#define OFF_QD   (BFTEN * 3)
#define OFF_KD   (BFTEN * 4)
#define OFF_PART (BFTEN * 5)
#define PART_SZ  ((size_t)32 * NCHUNK * 2400)
#define PLANE_FL 18432
#define OFF_WHI  (OFF_PART + PART_SZ)
#define TOTAL_SCRATCH (OFF_WHI + (size_t)11 * PLANE_FL)

__device__ __align__(256) float g_scratch[TOTAL_SCRATCH];

// ---------------- 3 weights -> bf16 planes --------------------------------------
__global__ void __launch_bounds__(256) wconv3(
    const float* __restrict__ w_q, const float* __restrict__ w_k,
    const float* __restrict__ w_v, __nv_bfloat16* __restrict__ dst)
{
    int mat = blockIdx.y;
    const float* src = mat == 0 ? w_q : mat == 1 ? w_k : w_v;
    dst += (size_t)mat * PLANE;
    for (int idx = blockIdx.x * 256 + threadIdx.x; idx < PLANE;
         idx += gridDim.x * 256)
        dst[idx] = __float2bfloat16(src[idx]);
}

// ---------------- mma / async helpers -------------------------------------------
__device__ __forceinline__ void mma_bf16(float* c, const uint32_t* a,
                                         const uint32_t* b)
{
    asm volatile(
        "mma.sync.aligned.m16n8k16.row.col.f32.bf16.bf16.f32 "
        "{%0,%1,%2,%3}, {%4,%5,%6,%7}, {%8,%9}, {%0,%1,%2,%3};"
        : "+f"(c[0]), "+f"(c[1]), "+f"(c[2]), "+f"(c[3])
        : "r"(a[0]), "r"(a[1]), "r"(a[2]), "r"(a[3]), "r"(b[0]), "r"(b[1]));
}
__device__ __forceinline__ void ldsm_x4(uint32_t* r, uint32_t addr)
{
    asm volatile("ldmatrix.sync.aligned.m8n8.x4.shared.b16 {%0,%1,%2,%3}, [%4];"
        : "=r"(r[0]), "=r"(r[1]), "=r"(r[2]), "=r"(r[3]) : "r"(addr));
}
__device__ __forceinline__ void ldsm_x2(uint32_t* r, uint32_t addr)
{
    asm volatile("ldmatrix.sync.aligned.m8n8.x2.shared.b16 {%0,%1}, [%2];"
        : "=r"(r[0]), "=r"(r[1]) : "r"(addr));
}
__device__ __forceinline__ void cp_async16(uint32_t dst, const void* src)
{
    asm volatile("cp.async.cg.shared.global [%0], [%1], 16;"
        :: "r"(dst), "l"(src) : "memory");
}
#define CP_COMMIT() asm volatile("cp.async.commit_group;" ::: "memory")
#define CP_WAIT(n)  asm volatile("cp.async.wait_group %0;" :: "n"(n) : "memory")

__device__ __forceinline__ uint32_t pack_bf2(float a, float b) {
    __nv_bfloat162 h = __floats2bfloat162_rn(a, b);
    return *reinterpret_cast<uint32_t*>(&h);
}

// ---------------- bf16 row load with shuffle halos -------------------------------
__device__ __forceinline__ void dw_load_row_bf(
    const __nv_bfloat16* __restrict__ ib, int y, int lane,
    float& l, float4& f, float& r)
{
    if ((unsigned)y < (unsigned)H_) {
        uint2 u = *reinterpret_cast<const uint2*>(ib + (size_t)y * W_ + lane * 4);
        __nv_bfloat162 lo = *reinterpret_cast<__nv_bfloat162*>(&u.x);
        __nv_bfloat162 hi = *reinterpret_cast<__nv_bfloat162*>(&u.y);
        f = make_float4(__bfloat162float(lo.x), __bfloat162float(lo.y),
                        __bfloat162float(hi.x), __bfloat162float(hi.y));
    } else {
        f = make_float4(0.f, 0.f, 0.f, 0.f);
    }
    float lw = __shfl_up_sync(0xffffffffu, f.w, 1);
    float rx = __shfl_down_sync(0xffffffffu, f.x, 1);
    l = (lane == 0)  ? 0.f : lw;
    r = (lane == 31) ? 0.f : rx;
}

// dwconv 3x3 for 4 pixels of row y, one channel plane
__device__ __forceinline__ float4 dw_row_out(
    const __nv_bfloat16* __restrict__ plane, const float* __restrict__ wp,
    int y, int lane)
{
    float w00 = __ldg(wp + 0), w01 = __ldg(wp + 1), w02 = __ldg(wp + 2);
    float w10 = __ldg(wp + 3), w11 = __ldg(wp + 4), w12 = __ldg(wp + 5);
    float w20 = __ldg(wp + 6), w21 = __ldg(wp + 7), w22 = __ldg(wp + 8);
    float pl, pr, cl, cr, nl, nr;
    float4 pf, cf, nf;
    dw_load_row_bf(plane, y - 1, lane, pl, pf, pr);
    dw_load_row_bf(plane, y,     lane, cl, cf, cr);
    dw_load_row_bf(plane, y + 1, lane, nl, nf, nr);
    float4 o;
    o.x = fmaf(pl,   w00, fmaf(pf.x, w01, fmaf(pf.y, w02,
          fmaf(cl,   w10, fmaf(cf.x, w11, fmaf(cf.y, w12,
          fmaf(nl,   w20, fmaf(nf.x, w21, nf.y * w22))))))));
    o.y = fmaf(pf.x, w00, fmaf(pf.y, w01, fmaf(pf.z, w02,
          fmaf(cf.x, w10, fmaf(cf.y, w11, fmaf(cf.z, w12,
          fmaf(nf.x, w20, fmaf(nf.y, w21, nf.z * w22))))))));
    o.z = fmaf(pf.y, w00, fmaf(pf.z, w01, fmaf(pf.w, w02,
          fmaf(cf.y, w10, fmaf(cf.z, w11, fmaf(cf.w, w12,
          fmaf(nf.y, w20, fmaf(nf.z, w21, nf.w * w22))))))));
    o.w = fmaf(pf.z, w00, fmaf(pf.w, w01, fmaf(pr,   w02,
          fmaf(cf.z, w10, fmaf(cf.w, w11, fmaf(cr,   w12,
          fmaf(nf.z, w20, fmaf(nf.w, w21, nr * w22))))))));
    return o;
}

// ---------------- GEMM mainloop + epilogue (shared tail) -------------------------
__device__ __forceinline__ void gemm_tail(
    uint32_t* sm, const __nv_bfloat16* wH, int mTiles,
    void* Out0, void* Out1, int outBf16, const float* R, int np0, int b)
{
    int tid  = threadIdx.x;
    int w    = tid >> 5, lane = tid & 31;
    int wm   = w >> 2,  wn = w & 3;
    int g    = lane >> 2, t = lane & 3;
    uint32_t smBase = (uint32_t)__cvta_generic_to_shared(sm);

    uint32_t baseB[2];
    #pragma unroll
    for (int in2 = 0; in2 < 2; in2++) {
        int row = wn * 32 + in2 * 16 + ((lane >> 4) << 3) + (lane & 7);
        baseB[in2] = smBase + (uint32_t)((row * 100 + ((lane >> 3) & 1) * 4) * 4);
    }

    auto copyA = [&](int mt, int buf) {
        #pragma unroll
        for (int i = 0; i < 6; i++) {
            int idx = tid + 256 * i;
            int row = idx / 24, j = idx % 24;
            size_t go = (size_t)(mt * 64 + row) * C_ + j * 8;
            uint32_t dst = smBase +
                (uint32_t)((12800 + buf * 6400 + row * 100 + j * 4) * 4);
            cp_async16(dst, &wH[go]);
        }
    };

    copyA(0, 0);
    CP_COMMIT();

    for (int mt = 0; mt < mTiles; mt++) {
        int buf = mt & 1;
        if (mt + 1 < mTiles) {
            copyA(mt + 1, buf ^ 1);
            CP_COMMIT();
            CP_WAIT(1);
        } else {
            CP_WAIT(0);
        }
        __syncthreads();

        uint32_t aB = smBase + (uint32_t)((12800 + buf * 6400) * 4);
        uint32_t baseA[2];
        #pragma unroll
        for (int im = 0; im < 2; im++) {
            int row = wm * 32 + im * 16 + (lane & 15);
            baseA[im] = aB + (uint32_t)(row * 400 + (lane >> 4) * 16);
        }

        float acc[8][4];
        #pragma unroll
        for (int i = 0; i < 8; i++)
            #pragma unroll
            for (int j = 0; j < 4; j++) acc[i][j] = 0.f;

        #pragma unroll
        for (int s = 0; s < 12; s++) {
            uint32_t ah[2][4], bh[2][4];
            #pragma unroll
            for (int im = 0; im < 2; im++)
                ldsm_x4(ah[im], baseA[im] + s * 32);
            #pragma unroll
            for (int in2 = 0; in2 < 2; in2++)
                ldsm_x4(bh[in2], baseB[in2] + s * 32);
            #pragma unroll
            for (int im = 0; im < 2; im++)
                #pragma unroll
                for (int in_ = 0; in_ < 4; in_++)
                    mma_bf16(acc[im * 4 + in_], ah[im],
                             &bh[in_ >> 1][(in_ & 1) * 2]);
        }

        #pragma unroll
        for (int im = 0; im < 2; im++) {
            #pragma unroll
            for (int in_ = 0; in_ < 4; in_++) {
                const float* c = acc[im * 4 + in_];
                int grow = mt * 64 + wm * 32 + im * 16 + g;
                int col  = np0 + wn * 32 + in_ * 8 + t * 2;
                #pragma unroll
                for (int half = 0; half < 2; half++) {
                    int rr = grow + half * 8;
                    float2 v = make_float2(c[half * 2], c[half * 2 + 1]);
                    size_t off = (size_t)b * C_ * HW_ +
                        (size_t)((rr < C_) ? rr : rr - C_) * HW_ + col;
                    if (outBf16) {
                        __nv_bfloat16* o = (rr < C_)
                            ? (__nv_bfloat16*)Out0 + off
                            : (__nv_bfloat16*)Out1 + off;
                        *reinterpret_cast<uint32_t*>(o) = pack_bf2(v.x, v.y);
                    } else {
                        float* o = (rr < C_) ? (float*)Out0 + off
                                             : (float*)Out1 + off;
                        if (R && rr < C_) {
                            const float2 r2 = *reinterpret_cast<const float2*>(
                                &R[(size_t)b * C_ * HW_ + (size_t)rr * HW_ + col]);
                            v.x += r2.x; v.y += r2.y;
                        }
                        *reinterpret_cast<float2*>(o) = v;
                    }
                }
            }
        }
        __syncthreads();
    }
}

// ---------------- merged q + kv producer GEMM (fused LN) -------------------------
__global__ void __launch_bounds__(256) mma_gemm_qkv(
    const float* __restrict__ q_in, const float* __restrict__ xx,
    const __nv_bfloat16* __restrict__ whi,
    __nv_bfloat16* __restrict__ qb, __nv_bfloat16* __restrict__ kb,
    __nv_bfloat16* __restrict__ vb,
    const float* __restrict__ gw, const float* __restrict__ gb)
{
    extern __shared__ uint32_t sm[];
    __shared__ float sP[256], ssP[256];
    uint32_t* Bh = sm;
    int tid = threadIdx.x;
    int np0 = blockIdx.x * 128;
    int b   = blockIdx.y;
    const float* X = blockIdx.z == 0 ? q_in : xx;

    // stage B: one global pass, LN fused
    {
        int p = tid & 127, kh = tid >> 7;
        const float* xc = X + (size_t)b * C_ * HW_ + np0 + p;
        float s = 0.f, ss = 0.f;
        #pragma unroll
        for (int i = 0; i < 48; i++) {
            int k = kh * 96 + i * 2;
            float x0 = xc[(size_t)k * HW_];
            float x1 = xc[(size_t)(k + 1) * HW_];
            s += x0 + x1;
            ss = fmaf(x0, x0, fmaf(x1, x1, ss));
            Bh[p * 100 + kh * 48 + i] = pack_bf2(x0, x1);
        }
        sP[tid] = s; ssP[tid] = ss;
        __syncthreads();
        float st  = sP[p] + sP[p + 128];
        float sst = ssP[p] + ssP[p + 128];
        float mu_ = st * (1.f / C_);
        float rs_ = rsqrtf(sst * (1.f / C_) - mu_ * mu_ + 1e-5f);
        #pragma unroll
        for (int i = 0; i < 48; i++) {
            int kp = kh * 48 + i, k = kp * 2;
            uint32_t u = Bh[p * 100 + kp];
            __nv_bfloat162 hv = *reinterpret_cast<__nv_bfloat162*>(&u);
            float x0 = __bfloat162float(hv.x);
            float x1 = __bfloat162float(hv.y);
            x0 = (x0 - mu_) * rs_ * __ldg(&gw[k])     + __ldg(&gb[k]);
            x1 = (x1 - mu_) * rs_ * __ldg(&gw[k + 1]) + __ldg(&gb[k + 1]);
            Bh[p * 100 + kp] = pack_bf2(x0, x1);
        }
    }

    if (blockIdx.z == 0)
        gemm_tail(sm, whi, 3, qb, qb, 1, nullptr, np0, b);
    else
        gemm_tail(sm, whi + PLANE, 6, kb, vb, 1, nullptr, np0, b);
}

// ---------------- final GEMM with FUSED dwconv(v) staging ------------------------
__global__ void __launch_bounds__(256) mma_gemm_fin(
    const __nv_bfloat16* __restrict__ vb,
    const float* __restrict__ wd_v,
    const __nv_bfloat16* __restrict__ whi,
    float* __restrict__ out, const float* __restrict__ q_in)
{
    extern __shared__ uint32_t sm[];
    uint32_t* Bh = sm;
    int tid = threadIdx.x;
    int w = tid >> 5, lane = tid & 31;
    int y   = blockIdx.x;               // 128-px tile == image row y
    int b   = blockIdx.y;
    const __nv_bfloat16* vbB = vb + (size_t)b * C_ * HW_;

    // stage B: dwconv(vb) computed on the fly; warp w handles channels [w*24..)
    #pragma unroll
    for (int pr = 0; pr < 12; pr++) {
        int k0 = w * 24 + pr * 2;
        float4 oA = dw_row_out(vbB + (size_t)k0 * HW_,       wd_v + k0 * 9,       y, lane);
        float4 oB = dw_row_out(vbB + (size_t)(k0 + 1) * HW_, wd_v + (k0 + 1) * 9, y, lane);
        int kp = k0 >> 1;
        int p = lane * 4;
        Bh[(p + 0) * 100 + kp] = pack_bf2(oA.x, oB.x);
        Bh[(p + 1) * 100 + kp] = pack_bf2(oA.y, oB.y);
        Bh[(p + 2) * 100 + kp] = pack_bf2(oA.z, oB.z);
        Bh[(p + 3) * 100 + kp] = pack_bf2(oA.w, oB.w);
    }
    __syncthreads();

    gemm_tail(sm, whi + (size_t)b * PLANE, 3, out, out, 0, q_in, y * 128, b);
}

// ---------------- depthwise 3x3 bf16 (q, k only) ---------------------------------
__global__ void __launch_bounds__(256) dw3v3(
    const __nv_bfloat16* __restrict__ inq, const __nv_bfloat16* __restrict__ ink,
    __nv_bfloat16* __restrict__ outq, __nv_bfloat16* __restrict__ outk,
    const float* __restrict__ wq, const float* __restrict__ wk)
{
    int which = blockIdx.y;
    const __nv_bfloat16* in  = which == 0 ? inq  : ink;
    __nv_bfloat16*       out = which == 0 ? outq : outk;
    const float*         wt  = which == 0 ? wq   : wk;

    int bc = blockIdx.x;
    int c  = bc % C_;
    const float* wp = wt + c * 9;
    float w00 = __ldg(wp + 0), w01 = __ldg(wp + 1), w02 = __ldg(wp + 2);
    float w10 = __ldg(wp + 3), w11 = __ldg(wp + 4), w12 = __ldg(wp + 5);
    float w20 = __ldg(wp + 6), w21 = __ldg(wp + 7), w22 = __ldg(wp + 8);

    int warp = threadIdx.x >> 5, lane = threadIdx.x & 31;
    int y0 = warp * 16;
    const __nv_bfloat16* ib = in + (size_t)bc * HW_;
    __nv_bfloat16* ob = out + (size_t)bc * HW_;

    float pl, pr, cl, cr, nl, nr;
    float4 pf, cf, nf;
    dw_load_row_bf(ib, y0 - 1, lane, pl, pf, pr);
    dw_load_row_bf(ib, y0,     lane, cl, cf, cr);

    #pragma unroll
    for (int r = 0; r < 16; r++) {
        int yy = y0 + r;
        dw_load_row_bf(ib, yy + 1, lane, nl, nf, nr);
        float4 o;
        o.x = fmaf(pl,   w00, fmaf(pf.x, w01, fmaf(pf.y, w02,
              fmaf(cl,   w10, fmaf(cf.x, w11, fmaf(cf.y, w12,
              fmaf(nl,   w20, fmaf(nf.x, w21, nf.y * w22))))))));
        o.y = fmaf(pf.x, w00, fmaf(pf.y, w01, fmaf(pf.z, w02,
              fmaf(cf.x, w10, fmaf(cf.y, w11, fmaf(cf.z, w12,
              fmaf(nf.x, w20, fmaf(nf.y, w21, nf.z * w22))))))));
        o.z = fmaf(pf.y, w00, fmaf(pf.z, w01, fmaf(pf.w, w02,
              fmaf(cf.y, w10, fmaf(cf.z, w11, fmaf(cf.w, w12,
              fmaf(nf.y, w20, fmaf(nf.z, w21, nf.w * w22))))))));
        o.w = fmaf(pf.z, w00, fmaf(pf.w, w01, fmaf(pr,   w02,
              fmaf(cf.z, w10, fmaf(cf.w, w11, fmaf(cr,   w12,
              fmaf(nf.z, w20, fmaf(nf.w, w21, nr * w22))))))));
        uint2 st;
        st.x = pack_bf2(o.x, o.y);
        st.y = pack_bf2(o.z, o.w);
        *reinterpret_cast<uint2*>(ob + (size_t)yy * W_ + lane * 4) = st;
        pl = cl; pr = cr; pf = cf;
        cl = nl; cr = nr; cf = nf;
    }
}

// ---------------- Gram via mma.sync (512-px chunks, 32 of them) ------------------
#define GR_STRIDE 36
#define GR_BUFW   (96 * GR_STRIDE)
__global__ void __launch_bounds__(256) gram_mma(
    const __nv_bfloat16* __restrict__ qd, const __nv_bfloat16* __restrict__ kd,
    float* __restrict__ part)
{
    __shared__ uint32_t gsm[2][GR_BUFW];
    __shared__ float nqs[96];

    int chunk = blockIdx.x;          // 0..31 (512 px each)
    int bh    = blockIdx.y;
    int b = bh >> 2, h = bh & 3;
    size_t base = ((size_t)b * C_ + h * DH) * HW_ + (size_t)chunk * 512;
    const __nv_bfloat16* qb_ = qd + base;
    const __nv_bfloat16* kb_ = kd + base;

    int tid = threadIdx.x;
    int w = tid >> 5, lane = tid & 31;
    int wm = w >> 1, wn = w & 1;
    int g = lane >> 2, t4 = lane & 3;
    uint32_t smBase = (uint32_t)__cvta_generic_to_shared(gsm);

    if (tid < 96) nqs[tid] = 0.f;

    int rowi[3], segi[3];
    #pragma unroll
    for (int it = 0; it < 3; it++) {
        int idx = tid + 256 * it;
        rowi[it] = idx >> 3;
        segi[it] = idx & 7;
    }
    float nacc[3] = {0.f, 0.f, 0.f};

    uint32_t offA = 0, offB4 = 0, offB2 = 0;
    if (w < 6) {
        int rA = wm * 16 + (lane & 15);
        offA = (uint32_t)((rA * GR_STRIDE + (lane >> 4) * 4) * 4);
        int rB4 = 48 + wn * 24 + ((lane >> 4) << 3) + (lane & 7);
        offB4 = (uint32_t)((rB4 * GR_STRIDE + ((lane >> 3) & 1) * 4) * 4);
        int l15 = lane & 15;
        int rB2 = 48 + wn * 24 + 16 + (l15 & 7);
        offB2 = (uint32_t)((rB2 * GR_STRIDE + ((l15 >> 3) & 1) * 4) * 4);
    }

    float acc[3][4];
    #pragma unroll
    for (int i = 0; i < 3; i++)
        #pragma unroll
        for (int j = 0; j < 4; j++) acc[i][j] = 0.f;

    uint4 rg[3];
    auto loadTile = [&](int t) {
        #pragma unroll
        for (int it = 0; it < 3; it++) {
            const __nv_bfloat16* src = (rowi[it] < 48)
                ? qb_ + (size_t)rowi[it] * HW_
                : kb_ + (size_t)(rowi[it] - 48) * HW_;
            rg[it] = *reinterpret_cast<const uint4*>(src + t * 64 + segi[it] * 8);
            const uint32_t* u = &rg[it].x;
            #pragma unroll
            for (int j = 0; j < 4; j++) {
                __nv_bfloat162 hv = *reinterpret_cast<const __nv_bfloat162*>(&u[j]);
                float a = __bfloat162float(hv.x), bb = __bfloat162float(hv.y);
                nacc[it] = fmaf(a, a, fmaf(bb, bb, nacc[it]));
            }
        }
    };
    auto storeTile = [&](int buf) {
        #pragma unroll
        for (int it = 0; it < 3; it++) {
            uint32_t* d = &gsm[buf][rowi[it] * GR_STRIDE + segi[it] * 4];
            d[0] = rg[it].x; d[1] = rg[it].y; d[2] = rg[it].z; d[3] = rg[it].w;
        }
    };

    loadTile(0);
    storeTile(0);

    for (int t = 0; t < 8; t++) {
        __syncthreads();
        if (t < 7) loadTile(t + 1);
        if (w < 6) {
            uint32_t bufOff = smBase + (uint32_t)((t & 1) * GR_BUFW * 4);
            #pragma unroll
            for (int s = 0; s < 4; s++) {
                uint32_t a[4], b4[4], b2[2];
                ldsm_x4(a,  bufOff + offA  + s * 32);
                ldsm_x4(b4, bufOff + offB4 + s * 32);
                ldsm_x2(b2, bufOff + offB2 + s * 32);
                mma_bf16(acc[0], a, &b4[0]);
                mma_bf16(acc[1], a, &b4[2]);
                mma_bf16(acc[2], a, b2);
            }
        }
        if (t < 7) {
            __syncthreads();
            storeTile((t + 1) & 1);
        }
    }

    #pragma unroll
    for (int it = 0; it < 3; it++)
        atomicAdd(&nqs[rowi[it]], nacc[it]);
    __syncthreads();

    float* pb = part + ((size_t)bh * NCHUNK + chunk) * 2400;
    if (w < 6) {
        int i0 = wm * 16;
        #pragma unroll
        for (int f = 0; f < 3; f++) {
            int n0 = wn * 24 + f * 8;
            pb[(i0 + g) * DH + n0 + t4 * 2]     = acc[f][0];
            pb[(i0 + g) * DH + n0 + t4 * 2 + 1] = acc[f][1];
            pb[(i0 + g + 8) * DH + n0 + t4 * 2]     = acc[f][2];
            pb[(i0 + g + 8) * DH + n0 + t4 * 2 + 1] = acc[f][3];
        }
    }
    if (tid < 96) pb[2304 + tid] = nqs[tid];
}

// ---------------- fused: reduce + softmax + build M (o-split, bf16 out) ----------
__global__ void __launch_bounds__(256) softmax_build(
    const float* __restrict__ part, const float* __restrict__ temp,
    const float* __restrict__ wp, __nv_bfloat16* __restrict__ M)
{
    int b = blockIdx.x;
    int oc = blockIdx.y;
    __shared__ float sA[HEADS][DH * DH];
    __shared__ float nq[DH], nk[DH];
    int tid = threadIdx.x;

    for (int h = 0; h < HEADS; h++) {
        int bh = b * HEADS + h;
        for (int e = tid; e < 2400; e += 256) {
            float s = 0.f;
            #pragma unroll
            for (int c = 0; c < NCHUNK; c++)
                s += part[((size_t)bh * NCHUNK + c) * 2400 + e];
            if (e < 2304)      sA[h][e] = s;
            else if (e < 2352) nq[e - 2304] = fmaxf(sqrtf(s), 1e-12f);
            else               nk[e - 2352] = fmaxf(sqrtf(s), 1e-12f);
        }
        __syncthreads();
        if (tid < DH) {
            int i = tid;
            float sc = __ldg(&temp[h]) / nq[i];
            float m = -1e30f;
            #pragma unroll 4
            for (int j = 0; j < DH; j++) {
                float s = sA[h][i * DH + j] * sc / nk[j];
                sA[h][i * DH + j] = s;
                m = fmaxf(m, s);
            }
            float sum = 0.f;
            #pragma unroll 4
            for (int j = 0; j < DH; j++) {
                float e = __expf(sA[h][i * DH + j] - m);
                sA[h][i * DH + j] = e;
                sum += e;
            }
            float rs = 1.f / sum;
            #pragma unroll 4
            for (int j = 0; j < DH; j++)
                sA[h][i * DH + j] *= rs;
        }
        __syncthreads();
    }

    for (int e = tid; e < 32 * C_; e += 256) {
        int o = oc * 32 + e / C_, cp = e % C_;
        int h = cp / DH, d = cp % DH;
        const float* wrow = wp + (size_t)o * C_ + h * DH;
        const float* arow = &sA[h][d];
        float s = 0.f;
        #pragma unroll
        for (int i = 0; i < DH; i++)
            s = fmaf(__ldg(&wrow[i]), arow[i * DH], s);
        M[(size_t)b * PLANE + (size_t)o * C_ + cp] = __float2bfloat16(s);
    }
}

// ---------------- launch --------------------------------------------------------
#define GEMM_SMEM 102400

extern "C" void kernel_launch(void* const* d_in, const int* in_sizes, int n_in,
                              void* d_out, int out_size)
{
    const float* xx     = (const float*)d_in[0];
    const float* q_in   = (const float*)d_in[1];
    const float* ln_w   = (const float*)d_in[2];
    const float* ln_b   = (const float*)d_in[3];
    const float* w_q    = (const float*)d_in[4];
    const float* w_k    = (const float*)d_in[5];
    const float* w_v    = (const float*)d_in[6];
    const float* wd_q   = (const float*)d_in[7];
    const float* wd_k   = (const float*)d_in[8];
    const float* wd_v   = (const float*)d_in[9];
    const float* w_proj = (const float*)d_in[10];
    const float* temp   = (const float*)d_in[11];
    float* out = (float*)d_out;

    float* S = nullptr;
    cudaGetSymbolAddress((void**)&S, g_scratch);
    __nv_bfloat16* qb = (__nv_bfloat16*)(S + OFF_QB);
    __nv_bfloat16* kb = (__nv_bfloat16*)(S + OFF_KB);
    __nv_bfloat16* vb = (__nv_bfloat16*)(S + OFF_VB);
    __nv_bfloat16* qd = (__nv_bfloat16*)(S + OFF_QD);
    __nv_bfloat16* kd = (__nv_bfloat16*)(S + OFF_KD);
    float* part = S + OFF_PART;
    __nv_bfloat16* whi = (__nv_bfloat16*)(S + OFF_WHI);

    cudaFuncSetAttribute(mma_gemm_qkv,
                         cudaFuncAttributeMaxDynamicSharedMemorySize, GEMM_SMEM);
    cudaFuncSetAttribute(mma_gemm_fin,
                         cudaFuncAttributeMaxDynamicSharedMemorySize, GEMM_SMEM);

    // 1. weights -> bf16 planes (slots 0..2)
    wconv3<<<dim3(36, 3), 256>>>(w_q, w_k, w_v, whi);

    // 2. q + kv GEMMs in one launch
    mma_gemm_qkv<<<dim3(HW_ / 128, B_, 2), 256, GEMM_SMEM>>>(
        q_in, xx, whi, qb, kb, vb, ln_w, ln_b);

    // 3. depthwise 3x3 for q, k only (v fused into final GEMM)
    dw3v3<<<dim3(B_ * C_, 2), 256>>>(qb, kb, qd, kd, wd_q, wd_k);

    // 4. Gram via tensor cores (32 chunks for wave balance)
    gram_mma<<<dim3(NCHUNK, 32), 256>>>(qd, kd, part);

    // 5. fused reduce + softmax + M build, o-split
    softmax_build<<<dim3(8, 6), 256>>>(part, temp, w_proj, whi + 3 * PLANE);

    // 6. final GEMM with fused dwconv(v) staging, fp32 out + residual
    mma_gemm_fin<<<dim3(HW_ / 128, B_), 256, GEMM_SMEM>>>(
        vb, wd_v, whi + 3 * PLANE, out, q_in);
}

// round 15
// speedup vs baseline: 1.1842x; 1.1842x over previous
#include <cuda_runtime.h>
#include <cuda_bf16.h>
#include <cstddef>
#include <cstdint>

#define B_    8
#define C_    192
#define H_    128
#define W_    128
#define HW_   16384
#define HEADS 4
#define DH    48
#define PLANE (C_ * C_)

// ---------------- scratch ----------------------------------------------------
#define TEN    ((size_t)B_ * C_ * HW_)
#define BFTEN  (TEN / 2)
#define OFF_QB   ((size_t)0)
#define OFF_KB   (BFTEN * 1)
#define OFF_VB   (BFTEN * 2)
#define OFF_QD   (BFTEN * 3)
#define OFF_KD   (BFTEN * 4)
#define OFF_VD   (BFTEN * 5)
#define OFF_PART (BFTEN * 6)
#define PART_SZ  ((size_t)32 * 16 * 2400)
#define PLANE_FL 18432
#define OFF_WHI  (OFF_PART + PART_SZ)
#define TOTAL_SCRATCH (OFF_WHI + (size_t)11 * PLANE_FL)

__device__ __align__(256) float g_scratch[TOTAL_SCRATCH];

// ---------------- 3 weights -> bf16 planes --------------------------------------
__global__ void __launch_bounds__(256) wconv3(
    const float* __restrict__ w_q, const float* __restrict__ w_k,
    const float* __restrict__ w_v, __nv_bfloat16* __restrict__ dst)
{
    int mat = blockIdx.y;
    const float* src = mat == 0 ? w_q : mat == 1 ? w_k : w_v;
    dst += (size_t)mat * PLANE;
    for (int idx = blockIdx.x * 256 + threadIdx.x; idx < PLANE;
         idx += gridDim.x * 256)
        dst[idx] = __float2bfloat16(src[idx]);
}

// ---------------- mma / async helpers -------------------------------------------
__device__ __forceinline__ void mma_bf16(float* c, const uint32_t* a,
                                         const uint32_t* b)
{
    asm volatile(
        "mma.sync.aligned.m16n8k16.row.col.f32.bf16.bf16.f32 "
        "{%0,%1,%2,%3}, {%4,%5,%6,%7}, {%8,%9}, {%0,%1,%2,%3};"
        : "+f"(c[0]), "+f"(c[1]), "+f"(c[2]), "+f"(c[3])
        : "r"(a[0]), "r"(a[1]), "r"(a[2]), "r"(a[3]), "r"(b[0]), "r"(b[1]));
}
__device__ __forceinline__ void ldsm_x4(uint32_t* r, uint32_t addr)
{
    asm volatile("ldmatrix.sync.aligned.m8n8.x4.shared.b16 {%0,%1,%2,%3}, [%4];"
        : "=r"(r[0]), "=r"(r[1]), "=r"(r[2]), "=r"(r[3]) : "r"(addr));
}
__device__ __forceinline__ void ldsm_x2(uint32_t* r, uint32_t addr)
{
    asm volatile("ldmatrix.sync.aligned.m8n8.x2.shared.b16 {%0,%1}, [%2];"
        : "=r"(r[0]), "=r"(r[1]) : "r"(addr));
}
__device__ __forceinline__ void cp_async16(uint32_t dst, const void* src)
{
    asm volatile("cp.async.cg.shared.global [%0], [%1], 16;"
        :: "r"(dst), "l"(src) : "memory");
}
#define CP_COMMIT() asm volatile("cp.async.commit_group;" ::: "memory")
#define CP_WAIT(n)  asm volatile("cp.async.wait_group %0;" :: "n"(n) : "memory")

__device__ __forceinline__ uint32_t pack_bf2(float a, float b) {
    __nv_bfloat162 h = __floats2bfloat162_rn(a, b);
    return *reinterpret_cast<uint32_t*>(&h);
}

// ---------------- shared GEMM body ----------------------------------------------
__device__ __forceinline__ void gemm_body(
    uint32_t* sm, float* sP, float* ssP,
    const void* __restrict__ Xv, int inBf16,
    const __nv_bfloat16* __restrict__ whi, int wStride, int mTiles,
    void* __restrict__ Out0, void* __restrict__ Out1, int outBf16,
    const float* __restrict__ R,
    const float* __restrict__ gw, const float* __restrict__ gb,
    int np0, int b)
{
    uint32_t* Bh = sm;
    int tid  = threadIdx.x;
    int w    = tid >> 5, lane = tid & 31;
    int wm   = w >> 2,  wn = w & 3;
    int g    = lane >> 2, t = lane & 3;
    const __nv_bfloat16* wH = whi + (size_t)b * wStride;
    uint32_t smBase = (uint32_t)__cvta_generic_to_shared(sm);

    {
        int p = tid & 127, kh = tid >> 7;
        if (inBf16) {
            const __nv_bfloat16* xc =
                (const __nv_bfloat16*)Xv + (size_t)b * C_ * HW_ + np0 + p;
            #pragma unroll
            for (int i = 0; i < 48; i++) {
                int kp = kh * 48 + i, k = kp * 2;
                union { __nv_bfloat16 h[2]; uint32_t u; } pk;
                pk.h[0] = xc[(size_t)k * HW_];
                pk.h[1] = xc[(size_t)(k + 1) * HW_];
                Bh[p * 100 + kp] = pk.u;
            }
        } else {
            const float* xc = (const float*)Xv + (size_t)b * C_ * HW_ + np0 + p;
            float s = 0.f, ss = 0.f;
            #pragma unroll
            for (int i = 0; i < 48; i++) {
                int k = kh * 96 + i * 2;
                float x0 = xc[(size_t)k * HW_];
                float x1 = xc[(size_t)(k + 1) * HW_];
                s += x0 + x1;
                ss = fmaf(x0, x0, fmaf(x1, x1, ss));
                Bh[p * 100 + kh * 48 + i] = pack_bf2(x0, x1);
            }
            sP[tid] = s; ssP[tid] = ss;
            __syncthreads();
            float st  = sP[p] + sP[p + 128];
            float sst = ssP[p] + ssP[p + 128];
            float mu_ = st * (1.f / C_);
            float rs_ = rsqrtf(sst * (1.f / C_) - mu_ * mu_ + 1e-5f);
            #pragma unroll
            for (int i = 0; i < 48; i++) {
                int kp = kh * 48 + i, k = kp * 2;
                uint32_t u = Bh[p * 100 + kp];
                __nv_bfloat162 hv = *reinterpret_cast<__nv_bfloat162*>(&u);
                float x0 = __bfloat162float(hv.x);
                float x1 = __bfloat162float(hv.y);
                x0 = (x0 - mu_) * rs_ * __ldg(&gw[k])     + __ldg(&gb[k]);
                x1 = (x1 - mu_) * rs_ * __ldg(&gw[k + 1]) + __ldg(&gb[k + 1]);
                Bh[p * 100 + kp] = pack_bf2(x0, x1);
            }
        }
    }

    uint32_t baseB[2];
    #pragma unroll
    for (int in2 = 0; in2 < 2; in2++) {
        int row = wn * 32 + in2 * 16 + ((lane >> 4) << 3) + (lane & 7);
        baseB[in2] = smBase + (uint32_t)((row * 100 + ((lane >> 3) & 1) * 4) * 4);
    }

    auto copyA = [&](int mt, int buf) {
        #pragma unroll
        for (int i = 0; i < 6; i++) {
            int idx = tid + 256 * i;
            int row = idx / 24, j = idx % 24;
            size_t go = (size_t)(mt * 64 + row) * C_ + j * 8;
            uint32_t dst = smBase +
                (uint32_t)((12800 + buf * 6400 + row * 100 + j * 4) * 4);
            cp_async16(dst, &wH[go]);
        }
    };

    copyA(0, 0);
    CP_COMMIT();

    for (int mt = 0; mt < mTiles; mt++) {
        int buf = mt & 1;
        if (mt + 1 < mTiles) {
            copyA(mt + 1, buf ^ 1);
            CP_COMMIT();
            CP_WAIT(1);
        } else {
            CP_WAIT(0);
        }
        __syncthreads();

        uint32_t aB = smBase + (uint32_t)((12800 + buf * 6400) * 4);
        uint32_t baseA[2];
        #pragma unroll
        for (int im = 0; im < 2; im++) {
            int row = wm * 32 + im * 16 + (lane & 15);
            baseA[im] = aB + (uint32_t)(row * 400 + (lane >> 4) * 16);
        }

        float acc[8][4];
        #pragma unroll
        for (int i = 0; i < 8; i++)
            #pragma unroll
            for (int j = 0; j < 4; j++) acc[i][j] = 0.f;

        #pragma unroll
        for (int s = 0; s < 12; s++) {
            uint32_t ah[2][4], bh[2][4];
            #pragma unroll
            for (int im = 0; im < 2; im++)
                ldsm_x4(ah[im], baseA[im] + s * 32);
            #pragma unroll
            for (int in2 = 0; in2 < 2; in2++)
                ldsm_x4(bh[in2], baseB[in2] + s * 32);
            #pragma unroll
            for (int im = 0; im < 2; im++)
                #pragma unroll
                for (int in_ = 0; in_ < 4; in_++)
                    mma_bf16(acc[im * 4 + in_], ah[im],
                             &bh[in_ >> 1][(in_ & 1) * 2]);
        }

        #pragma unroll
        for (int im = 0; im < 2; im++) {
            #pragma unroll
            for (int in_ = 0; in_ < 4; in_++) {
                const float* c = acc[im * 4 + in_];
                int grow = mt * 64 + wm * 32 + im * 16 + g;
                int col  = np0 + wn * 32 + in_ * 8 + t * 2;
                #pragma unroll
                for (int half = 0; half < 2; half++) {
                    int rr = grow + half * 8;
                    float2 v = make_float2(c[half * 2], c[half * 2 + 1]);
                    size_t off = (size_t)b * C_ * HW_ +
                        (size_t)((rr < C_) ? rr : rr - C_) * HW_ + col;
                    if (outBf16) {
                        __nv_bfloat16* o = (rr < C_)
                            ? (__nv_bfloat16*)Out0 + off
                            : (__nv_bfloat16*)Out1 + off;
                        *reinterpret_cast<uint32_t*>(o) = pack_bf2(v.x, v.y);
                    } else {
                        float* o = (rr < C_) ? (float*)Out0 + off
                                             : (float*)Out1 + off;
                        if (R && rr < C_) {
                            const float2 r2 = *reinterpret_cast<const float2*>(
                                &R[(size_t)b * C_ * HW_ + (size_t)rr * HW_ + col]);
                            v.x += r2.x; v.y += r2.y;
                        }
                        *reinterpret_cast<float2*>(o) = v;
                    }
                }
            }
        }
        __syncthreads();
    }
}

// ---------------- merged q + kv producer GEMM (job interleaved in x) -------------
__global__ void __launch_bounds__(256) mma_gemm_qkv(
    const float* __restrict__ q_in, const float* __restrict__ xx,
    const __nv_bfloat16* __restrict__ whi,
    __nv_bfloat16* __restrict__ qb, __nv_bfloat16* __restrict__ kb,
    __nv_bfloat16* __restrict__ vb,
    const float* __restrict__ gw, const float* __restrict__ gb)
{
    extern __shared__ uint32_t sm[];
    __shared__ float sP[256], ssP[256];
    int job = blockIdx.x & 1;            // interleave short/long CTAs
    int np0 = (blockIdx.x >> 1) * 128;
    int b   = blockIdx.y;
    if (job == 0)
        gemm_body(sm, sP, ssP, q_in, 0, whi, 0, 3, qb, qb, 1,
                  nullptr, gw, gb, np0, b);
    else
        gemm_body(sm, sP, ssP, xx, 0, whi + PLANE, 0, 6, kb, vb, 1,
                  nullptr, gw, gb, np0, b);
}

// ---------------- final GEMM ------------------------------------------------------
__global__ void __launch_bounds__(256) mma_gemm_fin(
    const __nv_bfloat16* __restrict__ vd,
    const __nv_bfloat16* __restrict__ whi,
    float* __restrict__ out, const float* __restrict__ q_in)
{
    extern __shared__ uint32_t sm[];
    __shared__ float sP[256], ssP[256];
    gemm_body(sm, sP, ssP, vd, 1, whi, PLANE, 3, out, out, 0,
              q_in, nullptr, nullptr, blockIdx.x * 128, blockIdx.y);
}

// ---------------- depthwise 3x3 bf16 ---------------------------------------------
__device__ __forceinline__ void dw_load_row_bf(
    const __nv_bfloat16* __restrict__ ib, int y, int lane,
    float& l, float4& f, float& r)
{
    if ((unsigned)y < (unsigned)H_) {
        uint2 u = *reinterpret_cast<const uint2*>(ib + (size_t)y * W_ + lane * 4);
        __nv_bfloat162 lo = *reinterpret_cast<__nv_bfloat162*>(&u.x);
        __nv_bfloat162 hi = *reinterpret_cast<__nv_bfloat162*>(&u.y);
        f = make_float4(__bfloat162float(lo.x), __bfloat162float(lo.y),
                        __bfloat162float(hi.x), __bfloat162float(hi.y));
    } else {
        f = make_float4(0.f, 0.f, 0.f, 0.f);
    }
    float lw = __shfl_up_sync(0xffffffffu, f.w, 1);
    float rx = __shfl_down_sync(0xffffffffu, f.x, 1);
    l = (lane == 0)  ? 0.f : lw;
    r = (lane == 31) ? 0.f : rx;
}

__global__ void __launch_bounds__(256) dw3v3(
    const __nv_bfloat16* __restrict__ inq, const __nv_bfloat16* __restrict__ ink,
    const __nv_bfloat16* __restrict__ inv,
    __nv_bfloat16* __restrict__ outq, __nv_bfloat16* __restrict__ outk,
    __nv_bfloat16* __restrict__ outv,
    const float* __restrict__ wq, const float* __restrict__ wk,
    const float* __restrict__ wv)
{
    int which = blockIdx.y;
    const __nv_bfloat16* in  = which == 0 ? inq  : which == 1 ? ink  : inv;
    __nv_bfloat16*       out = which == 0 ? outq : which == 1 ? outk : outv;
    const float*         wt  = which == 0 ? wq   : which == 1 ? wk   : wv;

    int bc = blockIdx.x;
    int c  = bc % C_;
    const float* wp = wt + c * 9;
    float w00 = __ldg(wp + 0), w01 = __ldg(wp + 1), w02 = __ldg(wp + 2);
    float w10 = __ldg(wp + 3), w11 = __ldg(wp + 4), w12 = __ldg(wp + 5);
    float w20 = __ldg(wp + 6), w21 = __ldg(wp + 7), w22 = __ldg(wp + 8);

    int warp = threadIdx.x >> 5, lane = threadIdx.x & 31;
    int y0 = warp * 16;
    const __nv_bfloat16* ib = in + (size_t)bc * HW_;
    __nv_bfloat16* ob = out + (size_t)bc * HW_;

    float pl, pr, cl, cr, nl, nr;
    float4 pf, cf, nf;
    dw_load_row_bf(ib, y0 - 1, lane, pl, pf, pr);
    dw_load_row_bf(ib, y0,     lane, cl, cf, cr);

    #pragma unroll
    for (int r = 0; r < 16; r++) {
        int y = y0 + r;
        dw_load_row_bf(ib, y + 1, lane, nl, nf, nr);
        float4 o;
        o.x = fmaf(pl,   w00, fmaf(pf.x, w01, fmaf(pf.y, w02,
              fmaf(cl,   w10, fmaf(cf.x, w11, fmaf(cf.y, w12,
              fmaf(nl,   w20, fmaf(nf.x, w21, nf.y * w22))))))));
        o.y = fmaf(pf.x, w00, fmaf(pf.y, w01, fmaf(pf.z, w02,
              fmaf(cf.x, w10, fmaf(cf.y, w11, fmaf(cf.z, w12,
              fmaf(nf.x, w20, fmaf(nf.y, w21, nf.z * w22))))))));
        o.z = fmaf(pf.y, w00, fmaf(pf.z, w01, fmaf(pf.w, w02,
              fmaf(cf.y, w10, fmaf(cf.z, w11, fmaf(cf.w, w12,
              fmaf(nf.y, w20, fmaf(nf.z, w21, nf.w * w22))))))));
        o.w = fmaf(pf.z, w00, fmaf(pf.w, w01, fmaf(pr,   w02,
              fmaf(cf.z, w10, fmaf(cf.w, w11, fmaf(cr,   w12,
              fmaf(nf.z, w20, fmaf(nf.w, w21, nr * w22))))))));
        uint2 st;
        st.x = pack_bf2(o.x, o.y);
        st.y = pack_bf2(o.z, o.w);
        *reinterpret_cast<uint2*>(ob + (size_t)y * W_ + lane * 4) = st;
        pl = cl; pr = cr; pf = cf;
        cl = nl; cr = nr; cf = nf;
    }
}

// ---------------- Gram via mma.sync (R11/R13 config: 64-px tiles, 16 chunks) -----
#define GR_STRIDE 36
#define GR_BUFW   (96 * GR_STRIDE)
__global__ void __launch_bounds__(256) gram_mma(
    const __nv_bfloat16* __restrict__ qd, const __nv_bfloat16* __restrict__ kd,
    float* __restrict__ part)
{
    __shared__ uint32_t gsm[2][GR_BUFW];
    __shared__ float nqs[96];

    int chunk = blockIdx.x;
    int bh    = blockIdx.y;
    int b = bh >> 2, h = bh & 3;
    size_t base = ((size_t)b * C_ + h * DH) * HW_ + (size_t)chunk * 1024;
    const __nv_bfloat16* qb_ = qd + base;
    const __nv_bfloat16* kb_ = kd + base;

    int tid = threadIdx.x;
    int w = tid >> 5, lane = tid & 31;
    int wm = w >> 1, wn = w & 1;
    int g = lane >> 2, t4 = lane & 3;
    uint32_t smBase = (uint32_t)__cvta_generic_to_shared(gsm);

    if (tid < 96) nqs[tid] = 0.f;

    int rowi[3], segi[3];
    #pragma unroll
    for (int it = 0; it < 3; it++) {
        int idx = tid + 256 * it;
        rowi[it] = idx >> 3;
        segi[it] = idx & 7;
    }
    float nacc[3] = {0.f, 0.f, 0.f};

    uint32_t offA = 0, offB4 = 0, offB2 = 0;
    if (w < 6) {
        int rA = wm * 16 + (lane & 15);
        offA = (uint32_t)((rA * GR_STRIDE + (lane >> 4) * 4) * 4);
        int rB4 = 48 + wn * 24 + ((lane >> 4) << 3) + (lane & 7);
        offB4 = (uint32_t)((rB4 * GR_STRIDE + ((lane >> 3) & 1) * 4) * 4);
        int l15 = lane & 15;
        int rB2 = 48 + wn * 24 + 16 + (l15 & 7);
        offB2 = (uint32_t)((rB2 * GR_STRIDE + ((l15 >> 3) & 1) * 4) * 4);
    }

    float acc[3][4];
    #pragma unroll
    for (int i = 0; i < 3; i++)
        #pragma unroll
        for (int j = 0; j < 4; j++) acc[i][j] = 0.f;

    uint4 rg[3];
    auto loadTile = [&](int t) {
        #pragma unroll
        for (int it = 0; it < 3; it++) {
            const __nv_bfloat16* src = (rowi[it] < 48)
                ? qb_ + (size_t)rowi[it] * HW_
                : kb_ + (size_t)(rowi[it] - 48) * HW_;
            rg[it] = *reinterpret_cast<const uint4*>(src + t * 64 + segi[it] * 8);
            const uint32_t* u = &rg[it].x;
            #pragma unroll
            for (int j = 0; j < 4; j++) {
                __nv_bfloat162 hv = *reinterpret_cast<const __nv_bfloat162*>(&u[j]);
                float a = __bfloat162float(hv.x), bb = __bfloat162float(hv.y);
                nacc[it] = fmaf(a, a, fmaf(bb, bb, nacc[it]));
            }
        }
    };
    auto storeTile = [&](int buf) {
        #pragma unroll
        for (int it = 0; it < 3; it++) {
            uint32_t* d = &gsm[buf][rowi[it] * GR_STRIDE + segi[it] * 4];
            d[0] = rg[it].x; d[1] = rg[it].y; d[2] = rg[it].z; d[3] = rg[it].w;
        }
    };

    loadTile(0);
    storeTile(0);

    for (int t = 0; t < 16; t++) {
        __syncthreads();
        if (t < 15) loadTile(t + 1);
        if (w < 6) {
            uint32_t bufOff = smBase + (uint32_t)((t & 1) * GR_BUFW * 4);
            #pragma unroll
            for (int s = 0; s < 4; s++) {
                uint32_t a[4], b4[4], b2[2];
                ldsm_x4(a,  bufOff + offA  + s * 32);
                ldsm_x4(b4, bufOff + offB4 + s * 32);
                ldsm_x2(b2, bufOff + offB2 + s * 32);
                mma_bf16(acc[0], a, &b4[0]);
                mma_bf16(acc[1], a, &b4[2]);
                mma_bf16(acc[2], a, b2);
            }
        }
        if (t < 15) {
            __syncthreads();
            storeTile((t + 1) & 1);
        }
    }

    #pragma unroll
    for (int it = 0; it < 3; it++)
        atomicAdd(&nqs[rowi[it]], nacc[it]);
    __syncthreads();

    float* pb = part + ((size_t)bh * 16 + chunk) * 2400;
    if (w < 6) {
        int i0 = wm * 16;
        #pragma unroll
        for (int f = 0; f < 3; f++) {
            int n0 = wn * 24 + f * 8;
            pb[(i0 + g) * DH + n0 + t4 * 2]     = acc[f][0];
            pb[(i0 + g) * DH + n0 + t4 * 2 + 1] = acc[f][1];
            pb[(i0 + g + 8) * DH + n0 + t4 * 2]     = acc[f][2];
            pb[(i0 + g + 8) * DH + n0 + t4 * 2 + 1] = acc[f][3];
        }
    }
    if (tid < 96) pb[2304 + tid] = nqs[tid];
}

// ---------------- fused: reduce + softmax + build M (o-split, bf16 out) ----------
__global__ void __launch_bounds__(256) softmax_build(
    const float* __restrict__ part, const float* __restrict__ temp,
    const float* __restrict__ wp, __nv_bfloat16* __restrict__ M)
{
    int b = blockIdx.x;
    int oc = blockIdx.y;
    __shared__ float sA[HEADS][DH * DH];
    __shared__ float nq[DH], nk[DH];
    int tid = threadIdx.x;

    for (int h = 0; h < HEADS; h++) {
        int bh = b * HEADS + h;
        for (int e = tid; e < 2400; e += 256) {
            float s = 0.f;
            #pragma unroll
            for (int c = 0; c < 16; c++)
                s += part[((size_t)bh * 16 + c) * 2400 + e];
            if (e < 2304)      sA[h][e] = s;
            else if (e < 2352) nq[e - 2304] = fmaxf(sqrtf(s), 1e-12f);
            else               nk[e - 2352] = fmaxf(sqrtf(s), 1e-12f);
        }
        __syncthreads();
        if (tid < DH) {
            int i = tid;
            float sc = __ldg(&temp[h]) / nq[i];
            float m = -1e30f;
            #pragma unroll 4
            for (int j = 0; j < DH; j++) {
                float s = sA[h][i * DH + j] * sc / nk[j];
                sA[h][i * DH + j] = s;
                m = fmaxf(m, s);
            }
            float sum = 0.f;
            #pragma unroll 4
            for (int j = 0; j < DH; j++) {
                float e = __expf(sA[h][i * DH + j] - m);
                sA[h][i * DH + j] = e;
                sum += e;
            }
            float rs = 1.f / sum;
            #pragma unroll 4
            for (int j = 0; j < DH; j++)
                sA[h][i * DH + j] *= rs;
        }
        __syncthreads();
    }

    for (int e = tid; e < 32 * C_; e += 256) {
        int o = oc * 32 + e / C_, cp = e % C_;
        int h = cp / DH, d = cp % DH;
        const float* wrow = wp + (size_t)o * C_ + h * DH;
        const float* arow = &sA[h][d];
        float s = 0.f;
        #pragma unroll
        for (int i = 0; i < DH; i++)
            s = fmaf(__ldg(&wrow[i]), arow[i * DH], s);
        M[(size_t)b * PLANE + (size_t)o * C_ + cp] = __float2bfloat16(s);
    }
}

// ---------------- launch --------------------------------------------------------
#define GEMM_SMEM 102400

extern "C" void kernel_launch(void* const* d_in, const int* in_sizes, int n_in,
                              void* d_out, int out_size)
{
    const float* xx     = (const float*)d_in[0];
    const float* q_in   = (const float*)d_in[1];
    const float* ln_w   = (const float*)d_in[2];
    const float* ln_b   = (const float*)d_in[3];
    const float* w_q    = (const float*)d_in[4];
    const float* w_k    = (const float*)d_in[5];
    const float* w_v    = (const float*)d_in[6];
    const float* wd_q   = (const float*)d_in[7];
    const float* wd_k   = (const float*)d_in[8];
    const float* wd_v   = (const float*)d_in[9];
    const float* w_proj = (const float*)d_in[10];
    const float* temp   = (const float*)d_in[11];
    float* out = (float*)d_out;

    float* S = nullptr;
    cudaGetSymbolAddress((void**)&S, g_scratch);
    __nv_bfloat16* qb = (__nv_bfloat16*)(S + OFF_QB);
    __nv_bfloat16* kb = (__nv_bfloat16*)(S + OFF_KB);
    __nv_bfloat16* vb = (__nv_bfloat16*)(S + OFF_VB);
    __nv_bfloat16* qd = (__nv_bfloat16*)(S + OFF_QD);
    __nv_bfloat16* kd = (__nv_bfloat16*)(S + OFF_KD);
    __nv_bfloat16* vd = (__nv_bfloat16*)(S + OFF_VD);
    float* part = S + OFF_PART;
    __nv_bfloat16* whi = (__nv_bfloat16*)(S + OFF_WHI);

    cudaFuncSetAttribute(mma_gemm_qkv,
                         cudaFuncAttributeMaxDynamicSharedMemorySize, GEMM_SMEM);
    cudaFuncSetAttribute(mma_gemm_fin,
                         cudaFuncAttributeMaxDynamicSharedMemorySize, GEMM_SMEM);

    // 1. weights -> bf16 planes (slots 0..2)
    wconv3<<<dim3(36, 3), 256>>>(w_q, w_k, w_v, whi);

    // 2. q + kv GEMMs in one launch, jobs interleaved in x
    mma_gemm_qkv<<<dim3((HW_ / 128) * 2, B_), 256, GEMM_SMEM>>>(
        q_in, xx, whi, qb, kb, vb, ln_w, ln_b);

    // 3. depthwise 3x3 (q, k, v)
    dw3v3<<<dim3(B_ * C_, 3), 256>>>(qb, kb, vb, qd, kd, vd, wd_q, wd_k, wd_v);

    // 4. Gram via tensor cores
    gram_mma<<<dim3(16, 32), 256>>>(qd, kd, part);

    // 5. fused reduce + softmax + M build, o-split
    softmax_build<<<dim3(8, 6), 256>>>(part, temp, w_proj, whi + 3 * PLANE);

    // 6. final GEMM fp32 + residual
    mma_gemm_fin<<<dim3(HW_ / 128, B_), 256, GEMM_SMEM>>>(
        vd, whi + 3 * PLANE, out, q_in);
}

// round 16
// speedup vs baseline: 1.2063x; 1.0186x over previous
#include <cuda_runtime.h>
#include <cuda_bf16.h>
#include <cstddef>
#include <cstdint>

#define B_    8
#define C_    192
#define H_    128
#define W_    128
#define HW_   16384
#define HEADS 4
#define DH    48
#define PLANE (C_ * C_)

// ---------------- scratch ----------------------------------------------------
#define TEN    ((size_t)B_ * C_ * HW_)
#define BFTEN  (TEN / 2)
#define OFF_QB   ((size_t)0)
#define OFF_KB   (BFTEN * 1)
#define OFF_VB   (BFTEN * 2)
#define OFF_QD   (BFTEN * 3)
#define OFF_KD   (BFTEN * 4)
#define OFF_VD   (BFTEN * 5)
#define OFF_PART (BFTEN * 6)
#define PART_SZ  ((size_t)32 * 16 * 2400)
#define PLANE_FL 18432
#define OFF_WHI  (OFF_PART + PART_SZ)
#define TOTAL_SCRATCH (OFF_WHI + (size_t)11 * PLANE_FL)

__device__ __align__(256) float g_scratch[TOTAL_SCRATCH];

// ---------------- 3 weights -> bf16 planes --------------------------------------
__global__ void __launch_bounds__(256) wconv3(
    const float* __restrict__ w_q, const float* __restrict__ w_k,
    const float* __restrict__ w_v, __nv_bfloat16* __restrict__ dst)
{
    int mat = blockIdx.y;
    const float* src = mat == 0 ? w_q : mat == 1 ? w_k : w_v;
    dst += (size_t)mat * PLANE;
    for (int idx = blockIdx.x * 256 + threadIdx.x; idx < PLANE;
         idx += gridDim.x * 256)
        dst[idx] = __float2bfloat16(src[idx]);
}

// ---------------- mma / async helpers -------------------------------------------
__device__ __forceinline__ void mma_bf16(float* c, const uint32_t* a,
                                         const uint32_t* b)
{
    asm volatile(
        "mma.sync.aligned.m16n8k16.row.col.f32.bf16.bf16.f32 "
        "{%0,%1,%2,%3}, {%4,%5,%6,%7}, {%8,%9}, {%0,%1,%2,%3};"
        : "+f"(c[0]), "+f"(c[1]), "+f"(c[2]), "+f"(c[3])
        : "r"(a[0]), "r"(a[1]), "r"(a[2]), "r"(a[3]), "r"(b[0]), "r"(b[1]));
}
__device__ __forceinline__ void ldsm_x4(uint32_t* r, uint32_t addr)
{
    asm volatile("ldmatrix.sync.aligned.m8n8.x4.shared.b16 {%0,%1,%2,%3}, [%4];"
        : "=r"(r[0]), "=r"(r[1]), "=r"(r[2]), "=r"(r[3]) : "r"(addr));
}
__device__ __forceinline__ void ldsm_x2(uint32_t* r, uint32_t addr)
{
    asm volatile("ldmatrix.sync.aligned.m8n8.x2.shared.b16 {%0,%1}, [%2];"
        : "=r"(r[0]), "=r"(r[1]) : "r"(addr));
}
__device__ __forceinline__ void cp_async16(uint32_t dst, const void* src)
{
    asm volatile("cp.async.cg.shared.global [%0], [%1], 16;"
        :: "r"(dst), "l"(src) : "memory");
}
#define CP_COMMIT() asm volatile("cp.async.commit_group;" ::: "memory")
#define CP_WAIT(n)  asm volatile("cp.async.wait_group %0;" :: "n"(n) : "memory")

__device__ __forceinline__ uint32_t pack_bf2(float a, float b) {
    __nv_bfloat162 h = __floats2bfloat162_rn(a, b);
    return *reinterpret_cast<uint32_t*>(&h);
}

// ---------------- shared GEMM body ----------------------------------------------
__device__ __forceinline__ void gemm_body(
    uint32_t* sm, float* sP, float* ssP,
    const void* __restrict__ Xv, int inBf16,
    const __nv_bfloat16* __restrict__ whi, int wStride, int mTiles,
    void* __restrict__ Out0, void* __restrict__ Out1, int outBf16,
    const float* __restrict__ R,
    const float* __restrict__ gw, const float* __restrict__ gb,
    int np0, int b)
{
    uint32_t* Bh = sm;
    int tid  = threadIdx.x;
    int w    = tid >> 5, lane = tid & 31;
    int wm   = w >> 2,  wn = w & 3;
    int g    = lane >> 2, t = lane & 3;
    const __nv_bfloat16* wH = whi + (size_t)b * wStride;
    uint32_t smBase = (uint32_t)__cvta_generic_to_shared(sm);

    {
        int p = tid & 127, kh = tid >> 7;
        if (inBf16) {
            const __nv_bfloat16* xc =
                (const __nv_bfloat16*)Xv + (size_t)b * C_ * HW_ + np0 + p;
            #pragma unroll
            for (int i = 0; i < 48; i++) {
                int kp = kh * 48 + i, k = kp * 2;
                union { __nv_bfloat16 h[2]; uint32_t u; } pk;
                pk.h[0] = xc[(size_t)k * HW_];
                pk.h[1] = xc[(size_t)(k + 1) * HW_];
                Bh[p * 100 + kp] = pk.u;
            }
        } else {
            const float* xc = (const float*)Xv + (size_t)b * C_ * HW_ + np0 + p;
            float s = 0.f, ss = 0.f;
            #pragma unroll
            for (int i = 0; i < 48; i++) {
                int k = kh * 96 + i * 2;
                float x0 = xc[(size_t)k * HW_];
                float x1 = xc[(size_t)(k + 1) * HW_];
                s += x0 + x1;
                ss = fmaf(x0, x0, fmaf(x1, x1, ss));
                Bh[p * 100 + kh * 48 + i] = pack_bf2(x0, x1);
            }
            sP[tid] = s; ssP[tid] = ss;
            __syncthreads();
            float st  = sP[p] + sP[p + 128];
            float sst = ssP[p] + ssP[p + 128];
            float mu_ = st * (1.f / C_);
            float rs_ = rsqrtf(sst * (1.f / C_) - mu_ * mu_ + 1e-5f);
            const float2* gw2 = (const float2*)gw;
            const float2* gb2 = (const float2*)gb;
            #pragma unroll
            for (int i = 0; i < 48; i++) {
                int kp = kh * 48 + i;
                uint32_t u = Bh[p * 100 + kp];
                __nv_bfloat162 hv = *reinterpret_cast<__nv_bfloat162*>(&u);
                float x0 = __bfloat162float(hv.x);
                float x1 = __bfloat162float(hv.y);
                float2 gwp = __ldg(&gw2[kp]);
                float2 gbp = __ldg(&gb2[kp]);
                x0 = (x0 - mu_) * rs_ * gwp.x + gbp.x;
                x1 = (x1 - mu_) * rs_ * gwp.y + gbp.y;
                Bh[p * 100 + kp] = pack_bf2(x0, x1);
            }
        }
    }

    uint32_t baseB[2];
    #pragma unroll
    for (int in2 = 0; in2 < 2; in2++) {
        int row = wn * 32 + in2 * 16 + ((lane >> 4) << 3) + (lane & 7);
        baseB[in2] = smBase + (uint32_t)((row * 100 + ((lane >> 3) & 1) * 4) * 4);
    }

    auto copyA = [&](int mt, int buf) {
        #pragma unroll
        for (int i = 0; i < 6; i++) {
            int idx = tid + 256 * i;
            int row = idx / 24, j = idx % 24;
            size_t go = (size_t)(mt * 64 + row) * C_ + j * 8;
            uint32_t dst = smBase +
                (uint32_t)((12800 + buf * 6400 + row * 100 + j * 4) * 4);
            cp_async16(dst, &wH[go]);
        }
    };

    copyA(0, 0);
    CP_COMMIT();

    for (int mt = 0; mt < mTiles; mt++) {
        int buf = mt & 1;
        if (mt + 1 < mTiles) {
            copyA(mt + 1, buf ^ 1);
            CP_COMMIT();
            CP_WAIT(1);
        } else {
            CP_WAIT(0);
        }
        __syncthreads();

        uint32_t aB = smBase + (uint32_t)((12800 + buf * 6400) * 4);
        uint32_t baseA[2];
        #pragma unroll
        for (int im = 0; im < 2; im++) {
            int row = wm * 32 + im * 16 + (lane & 15);
            baseA[im] = aB + (uint32_t)(row * 400 + (lane >> 4) * 16);
        }

        float acc[8][4];
        #pragma unroll
        for (int i = 0; i < 8; i++)
            #pragma unroll
            for (int j = 0; j < 4; j++) acc[i][j] = 0.f;

        #pragma unroll
        for (int s = 0; s < 12; s++) {
            uint32_t ah[2][4], bh[2][4];
            #pragma unroll
            for (int im = 0; im < 2; im++)
                ldsm_x4(ah[im], baseA[im] + s * 32);
            #pragma unroll
            for (int in2 = 0; in2 < 2; in2++)
                ldsm_x4(bh[in2], baseB[in2] + s * 32);
            #pragma unroll
            for (int im = 0; im < 2; im++)
                #pragma unroll
                for (int in_ = 0; in_ < 4; in_++)
                    mma_bf16(acc[im * 4 + in_], ah[im],
                             &bh[in_ >> 1][(in_ & 1) * 2]);
        }

        #pragma unroll
        for (int im = 0; im < 2; im++) {
            #pragma unroll
            for (int in_ = 0; in_ < 4; in_++) {
                const float* c = acc[im * 4 + in_];
                int grow = mt * 64 + wm * 32 + im * 16 + g;
                int col  = np0 + wn * 32 + in_ * 8 + t * 2;
                #pragma unroll
                for (int half = 0; half < 2; half++) {
                    int rr = grow + half * 8;
                    float2 v = make_float2(c[half * 2], c[half * 2 + 1]);
                    size_t off = (size_t)b * C_ * HW_ +
                        (size_t)((rr < C_) ? rr : rr - C_) * HW_ + col;
                    if (outBf16) {
                        __nv_bfloat16* o = (rr < C_)
                            ? (__nv_bfloat16*)Out0 + off
                            : (__nv_bfloat16*)Out1 + off;
                        *reinterpret_cast<uint32_t*>(o) = pack_bf2(v.x, v.y);
                    } else {
                        float* o = (rr < C_) ? (float*)Out0 + off
                                             : (float*)Out1 + off;
                        if (R && rr < C_) {
                            const float2 r2 = *reinterpret_cast<const float2*>(
                                &R[(size_t)b * C_ * HW_ + (size_t)rr * HW_ + col]);
                            v.x += r2.x; v.y += r2.y;
                        }
                        *reinterpret_cast<float2*>(o) = v;
                    }
                }
            }
        }
        __syncthreads();
    }
}

// ---------------- merged q + kv producer GEMM (LONG job first) -------------------
__global__ void __launch_bounds__(256) mma_gemm_qkv(
    const float* __restrict__ q_in, const float* __restrict__ xx,
    const __nv_bfloat16* __restrict__ whi,
    __nv_bfloat16* __restrict__ qb, __nv_bfloat16* __restrict__ kb,
    __nv_bfloat16* __restrict__ vb,
    const float* __restrict__ gw, const float* __restrict__ gb)
{
    extern __shared__ uint32_t sm[];
    __shared__ float sP[256], ssP[256];
    int np0 = blockIdx.x * 128;
    int b   = blockIdx.y;
    if (blockIdx.z == 0)   // long kv job first -> tail filled by short q CTAs
        gemm_body(sm, sP, ssP, xx, 0, whi + PLANE, 0, 6, kb, vb, 1,
                  nullptr, gw, gb, np0, b);
    else
        gemm_body(sm, sP, ssP, q_in, 0, whi, 0, 3, qb, qb, 1,
                  nullptr, gw, gb, np0, b);
}

// ---------------- final GEMM ------------------------------------------------------
__global__ void __launch_bounds__(256) mma_gemm_fin(
    const __nv_bfloat16* __restrict__ vd,
    const __nv_bfloat16* __restrict__ whi,
    float* __restrict__ out, const float* __restrict__ q_in)
{
    extern __shared__ uint32_t sm[];
    __shared__ float sP[256], ssP[256];
    gemm_body(sm, sP, ssP, vd, 1, whi, PLANE, 3, out, out, 0,
              q_in, nullptr, nullptr, blockIdx.x * 128, blockIdx.y);
}

// ---------------- depthwise 3x3 bf16 ---------------------------------------------
__device__ __forceinline__ void dw_load_row_bf(
    const __nv_bfloat16* __restrict__ ib, int y, int lane,
    float& l, float4& f, float& r)
{
    if ((unsigned)y < (unsigned)H_) {
        uint2 u = *reinterpret_cast<const uint2*>(ib + (size_t)y * W_ + lane * 4);
        __nv_bfloat162 lo = *reinterpret_cast<__nv_bfloat162*>(&u.x);
        __nv_bfloat162 hi = *reinterpret_cast<__nv_bfloat162*>(&u.y);
        f = make_float4(__bfloat162float(lo.x), __bfloat162float(lo.y),
                        __bfloat162float(hi.x), __bfloat162float(hi.y));
    } else {
        f = make_float4(0.f, 0.f, 0.f, 0.f);
    }
    float lw = __shfl_up_sync(0xffffffffu, f.w, 1);
    float rx = __shfl_down_sync(0xffffffffu, f.x, 1);
    l = (lane == 0)  ? 0.f : lw;
    r = (lane == 31) ? 0.f : rx;
}

__global__ void __launch_bounds__(256) dw3v3(
    const __nv_bfloat16* __restrict__ inq, const __nv_bfloat16* __restrict__ ink,
    const __nv_bfloat16* __restrict__ inv,
    __nv_bfloat16* __restrict__ outq, __nv_bfloat16* __restrict__ outk,
    __nv_bfloat16* __restrict__ outv,
    const float* __restrict__ wq, const float* __restrict__ wk,
    const float* __restrict__ wv)
{
    int which = blockIdx.y;
    const __nv_bfloat16* in  = which == 0 ? inq  : which == 1 ? ink  : inv;
    __nv_bfloat16*       out = which == 0 ? outq : which == 1 ? outk : outv;
    const float*         wt  = which == 0 ? wq   : which == 1 ? wk   : wv;

    int bc = blockIdx.x;
    int c  = bc % C_;
    const float* wp = wt + c * 9;
    float w00 = __ldg(wp + 0), w01 = __ldg(wp + 1), w02 = __ldg(wp + 2);
    float w10 = __ldg(wp + 3), w11 = __ldg(wp + 4), w12 = __ldg(wp + 5);
    float w20 = __ldg(wp + 6), w21 = __ldg(wp + 7), w22 = __ldg(wp + 8);

    int warp = threadIdx.x >> 5, lane = threadIdx.x & 31;
    int y0 = warp * 16;
    const __nv_bfloat16* ib = in + (size_t)bc * HW_;
    __nv_bfloat16* ob = out + (size_t)bc * HW_;

    float pl, pr, cl, cr, nl, nr;
    float4 pf, cf, nf;
    dw_load_row_bf(ib, y0 - 1, lane, pl, pf, pr);
    dw_load_row_bf(ib, y0,     lane, cl, cf, cr);

    #pragma unroll
    for (int r = 0; r < 16; r++) {
        int y = y0 + r;
        dw_load_row_bf(ib, y + 1, lane, nl, nf, nr);
        float4 o;
        o.x = fmaf(pl,   w00, fmaf(pf.x, w01, fmaf(pf.y, w02,
              fmaf(cl,   w10, fmaf(cf.x, w11, fmaf(cf.y, w12,
              fmaf(nl,   w20, fmaf(nf.x, w21, nf.y * w22))))))));
        o.y = fmaf(pf.x, w00, fmaf(pf.y, w01, fmaf(pf.z, w02,
              fmaf(cf.x, w10, fmaf(cf.y, w11, fmaf(cf.z, w12,
              fmaf(nf.x, w20, fmaf(nf.y, w21, nf.z * w22))))))));
        o.z = fmaf(pf.y, w00, fmaf(pf.z, w01, fmaf(pf.w, w02,
              fmaf(cf.y, w10, fmaf(cf.z, w11, fmaf(cf.w, w12,
              fmaf(nf.y, w20, fmaf(nf.z, w21, nf.w * w22))))))));
        o.w = fmaf(pf.z, w00, fmaf(pf.w, w01, fmaf(pr,   w02,
              fmaf(cf.z, w10, fmaf(cf.w, w11, fmaf(cr,   w12,
              fmaf(nf.z, w20, fmaf(nf.w, w21, nr * w22))))))));
        uint2 st;
        st.x = pack_bf2(o.x, o.y);
        st.y = pack_bf2(o.z, o.w);
        *reinterpret_cast<uint2*>(ob + (size_t)y * W_ + lane * 4) = st;
        pl = cl; pr = cr; pf = cf;
        cl = nl; cr = nr; cf = nf;
    }
}

// ---------------- Gram via mma.sync (64-px tiles, 16 chunks) ---------------------
#define GR_STRIDE 36
#define GR_BUFW   (96 * GR_STRIDE)
__global__ void __launch_bounds__(256) gram_mma(
    const __nv_bfloat16* __restrict__ qd, const __nv_bfloat16* __restrict__ kd,
    float* __restrict__ part)
{
    __shared__ uint32_t gsm[2][GR_BUFW];
    __shared__ float nqs[96];

    int chunk = blockIdx.x;
    int bh    = blockIdx.y;
    int b = bh >> 2, h = bh & 3;
    size_t base = ((size_t)b * C_ + h * DH) * HW_ + (size_t)chunk * 1024;
    const __nv_bfloat16* qb_ = qd + base;
    const __nv_bfloat16* kb_ = kd + base;

    int tid = threadIdx.x;
    int w = tid >> 5, lane = tid & 31;
    int wm = w >> 1, wn = w & 1;
    int g = lane >> 2, t4 = lane & 3;
    uint32_t smBase = (uint32_t)__cvta_generic_to_shared(gsm);

    if (tid < 96) nqs[tid] = 0.f;

    int rowi[3], segi[3];
    #pragma unroll
    for (int it = 0; it < 3; it++) {
        int idx = tid + 256 * it;
        rowi[it] = idx >> 3;
        segi[it] = idx & 7;
    }
    float naccA[3] = {0.f, 0.f, 0.f};
    float naccB[3] = {0.f, 0.f, 0.f};

    uint32_t offA = 0, offB4 = 0, offB2 = 0;
    if (w < 6) {
        int rA = wm * 16 + (lane & 15);
        offA = (uint32_t)((rA * GR_STRIDE + (lane >> 4) * 4) * 4);
        int rB4 = 48 + wn * 24 + ((lane >> 4) << 3) + (lane & 7);
        offB4 = (uint32_t)((rB4 * GR_STRIDE + ((lane >> 3) & 1) * 4) * 4);
        int l15 = lane & 15;
        int rB2 = 48 + wn * 24 + 16 + (l15 & 7);
        offB2 = (uint32_t)((rB2 * GR_STRIDE + ((l15 >> 3) & 1) * 4) * 4);
    }

    float acc[3][4];
    #pragma unroll
    for (int i = 0; i < 3; i++)
        #pragma unroll
        for (int j = 0; j < 4; j++) acc[i][j] = 0.f;

    uint4 rg[3];
    auto loadTile = [&](int t) {
        #pragma unroll
        for (int it = 0; it < 3; it++) {
            const __nv_bfloat16* src = (rowi[it] < 48)
                ? qb_ + (size_t)rowi[it] * HW_
                : kb_ + (size_t)(rowi[it] - 48) * HW_;
            rg[it] = *reinterpret_cast<const uint4*>(src + t * 64 + segi[it] * 8);
            const uint32_t* u = &rg[it].x;
            // sum-of-squares with two independent chains (ILP)
            __nv_bfloat162 h0 = *reinterpret_cast<const __nv_bfloat162*>(&u[0]);
            __nv_bfloat162 h1 = *reinterpret_cast<const __nv_bfloat162*>(&u[1]);
            __nv_bfloat162 h2 = *reinterpret_cast<const __nv_bfloat162*>(&u[2]);
            __nv_bfloat162 h3 = *reinterpret_cast<const __nv_bfloat162*>(&u[3]);
            float a0 = __bfloat162float(h0.x), a1 = __bfloat162float(h0.y);
            float a2 = __bfloat162float(h1.x), a3 = __bfloat162float(h1.y);
            float b0 = __bfloat162float(h2.x), b1 = __bfloat162float(h2.y);
            float b2 = __bfloat162float(h3.x), b3 = __bfloat162float(h3.y);
            naccA[it] = fmaf(a0, a0, fmaf(a1, a1,
                        fmaf(a2, a2, fmaf(a3, a3, naccA[it]))));
            naccB[it] = fmaf(b0, b0, fmaf(b1, b1,
                        fmaf(b2, b2, fmaf(b3, b3, naccB[it]))));
        }
    };
    auto storeTile = [&](int buf) {
        #pragma unroll
        for (int it = 0; it < 3; it++) {
            uint32_t* d = &gsm[buf][rowi[it] * GR_STRIDE + segi[it] * 4];
            d[0] = rg[it].x; d[1] = rg[it].y; d[2] = rg[it].z; d[3] = rg[it].w;
        }
    };

    loadTile(0);
    storeTile(0);

    for (int t = 0; t < 16; t++) {
        __syncthreads();
        if (t < 15) loadTile(t + 1);
        if (w < 6) {
            uint32_t bufOff = smBase + (uint32_t)((t & 1) * GR_BUFW * 4);
            #pragma unroll
            for (int s = 0; s < 4; s++) {
                uint32_t a[4], b4[4], b2[2];
                ldsm_x4(a,  bufOff + offA  + s * 32);
                ldsm_x4(b4, bufOff + offB4 + s * 32);
                ldsm_x2(b2, bufOff + offB2 + s * 32);
                mma_bf16(acc[0], a, &b4[0]);
                mma_bf16(acc[1], a, &b4[2]);
                mma_bf16(acc[2], a, b2);
            }
        }
        if (t < 15) {
            __syncthreads();
            storeTile((t + 1) & 1);
        }
    }

    #pragma unroll
    for (int it = 0; it < 3; it++)
        atomicAdd(&nqs[rowi[it]], naccA[it] + naccB[it]);
    __syncthreads();

    float* pb = part + ((size_t)bh * 16 + chunk) * 2400;
    if (w < 6) {
        int i0 = wm * 16;
        #pragma unroll
        for (int f = 0; f < 3; f++) {
            int n0 = wn * 24 + f * 8;
            pb[(i0 + g) * DH + n0 + t4 * 2]     = acc[f][0];
            pb[(i0 + g) * DH + n0 + t4 * 2 + 1] = acc[f][1];
            pb[(i0 + g + 8) * DH + n0 + t4 * 2]     = acc[f][2];
            pb[(i0 + g + 8) * DH + n0 + t4 * 2 + 1] = acc[f][3];
        }
    }
    if (tid < 96) pb[2304 + tid] = nqs[tid];
}

// ---------------- fused: reduce + softmax + build M (o-split, bf16 out) ----------
__global__ void __launch_bounds__(256) softmax_build(
    const float* __restrict__ part, const float* __restrict__ temp,
    const float* __restrict__ wp, __nv_bfloat16* __restrict__ M)
{
    int b = blockIdx.x;
    int oc = blockIdx.y;
    __shared__ float sA[HEADS][DH * DH];
    __shared__ float nq[DH], nk[DH];
    int tid = threadIdx.x;

    for (int h = 0; h < HEADS; h++) {
        int bh = b * HEADS + h;
        for (int e = tid; e < 2400; e += 256) {
            float s = 0.f;
            #pragma unroll
            for (int c = 0; c < 16; c++)
                s += part[((size_t)bh * 16 + c) * 2400 + e];
            if (e < 2304)      sA[h][e] = s;
            else if (e < 2352) nq[e - 2304] = fmaxf(sqrtf(s), 1e-12f);
            else               nk[e - 2352] = fmaxf(sqrtf(s), 1e-12f);
        }
        __syncthreads();
        if (tid < DH) {
            int i = tid;
            float sc = __ldg(&temp[h]) / nq[i];
            float m = -1e30f;
            #pragma unroll 4
            for (int j = 0; j < DH; j++) {
                float s = sA[h][i * DH + j] * sc / nk[j];
                sA[h][i * DH + j] = s;
                m = fmaxf(m, s);
            }
            float sum = 0.f;
            #pragma unroll 4
            for (int j = 0; j < DH; j++) {
                float e = __expf(sA[h][i * DH + j] - m);
                sA[h][i * DH + j] = e;
                sum += e;
            }
            float rs = 1.f / sum;
            #pragma unroll 4
            for (int j = 0; j < DH; j++)
                sA[h][i * DH + j] *= rs;
        }
        __syncthreads();
    }

    for (int e = tid; e < 32 * C_; e += 256) {
        int o = oc * 32 + e / C_, cp = e % C_;
        int h = cp / DH, d = cp % DH;
        const float* wrow = wp + (size_t)o * C_ + h * DH;
        const float* arow = &sA[h][d];
        float s = 0.f;
        #pragma unroll
        for (int i = 0; i < DH; i++)
            s = fmaf(__ldg(&wrow[i]), arow[i * DH], s);
        M[(size_t)b * PLANE + (size_t)o * C_ + cp] = __float2bfloat16(s);
    }
}

// ---------------- launch --------------------------------------------------------
#define GEMM_SMEM 102400

extern "C" void kernel_launch(void* const* d_in, const int* in_sizes, int n_in,
                              void* d_out, int out_size)
{
    const float* xx     = (const float*)d_in[0];
    const float* q_in   = (const float*)d_in[1];
    const float* ln_w   = (const float*)d_in[2];
    const float* ln_b   = (const float*)d_in[3];
    const float* w_q    = (const float*)d_in[4];
    const float* w_k    = (const float*)d_in[5];
    const float* w_v    = (const float*)d_in[6];
    const float* wd_q   = (const float*)d_in[7];
    const float* wd_k   = (const float*)d_in[8];
    const float* wd_v   = (const float*)d_in[9];
    const float* w_proj = (const float*)d_in[10];
    const float* temp   = (const float*)d_in[11];
    float* out = (float*)d_out;

    float* S = nullptr;
    cudaGetSymbolAddress((void**)&S, g_scratch);
    __nv_bfloat16* qb = (__nv_bfloat16*)(S + OFF_QB);
    __nv_bfloat16* kb = (__nv_bfloat16*)(S + OFF_KB);
    __nv_bfloat16* vb = (__nv_bfloat16*)(S + OFF_VB);
    __nv_bfloat16* qd = (__nv_bfloat16*)(S + OFF_QD);
    __nv_bfloat16* kd = (__nv_bfloat16*)(S + OFF_KD);
    __nv_bfloat16* vd = (__nv_bfloat16*)(S + OFF_VD);
    float* part = S + OFF_PART;
    __nv_bfloat16* whi = (__nv_bfloat16*)(S + OFF_WHI);

    cudaFuncSetAttribute(mma_gemm_qkv,
                         cudaFuncAttributeMaxDynamicSharedMemorySize, GEMM_SMEM);
    cudaFuncSetAttribute(mma_gemm_fin,
                         cudaFuncAttributeMaxDynamicSharedMemorySize, GEMM_SMEM);

    // 1. weights -> bf16 planes (slots 0..2)
    wconv3<<<dim3(36, 3), 256>>>(w_q, w_k, w_v, whi);

    // 2. q + kv GEMMs in one launch (z=0: long kv job first)
    mma_gemm_qkv<<<dim3(HW_ / 128, B_, 2), 256, GEMM_SMEM>>>(
        q_in, xx, whi, qb, kb, vb, ln_w, ln_b);

    // 3. depthwise 3x3 (q, k, v)
    dw3v3<<<dim3(B_ * C_, 3), 256>>>(qb, kb, vb, qd, kd, vd, wd_q, wd_k, wd_v);

    // 4. Gram via tensor cores
    gram_mma<<<dim3(16, 32), 256>>>(qd, kd, part);

    // 5. fused reduce + softmax + M build, o-split
    softmax_build<<<dim3(8, 6), 256>>>(part, temp, w_proj, whi + 3 * PLANE);

    // 6. final GEMM fp32 + residual
    mma_gemm_fin<<<dim3(HW_ / 128, B_), 256, GEMM_SMEM>>>(
        vd, whi + 3 * PLANE, out, q_in);
}

// round 17
// speedup vs baseline: 1.2074x; 1.0010x over previous
#include <cuda_runtime.h>
#include <cuda_bf16.h>
#include <cstddef>
#include <cstdint>

#define B_    8
#define C_    192
#define H_    128
#define W_    128
#define HW_   16384
#define HEADS 4
#define DH    48
#define PLANE (C_ * C_)

// ---------------- scratch ----------------------------------------------------
#define TEN    ((size_t)B_ * C_ * HW_)
#define BFTEN  (TEN / 2)
#define OFF_QB   ((size_t)0)
#define OFF_KB   (BFTEN * 1)
#define OFF_VB   (BFTEN * 2)
#define OFF_QD   (BFTEN * 3)
#define OFF_KD   (BFTEN * 4)
#define OFF_VD   (BFTEN * 5)
#define OFF_PART (BFTEN * 6)
#define PART_SZ  ((size_t)32 * 16 * 2400)
#define PLANE_FL 18432
#define OFF_WHI  (OFF_PART + PART_SZ)
#define TOTAL_SCRATCH (OFF_WHI + (size_t)11 * PLANE_FL)

__device__ __align__(256) float g_scratch[TOTAL_SCRATCH];

// ---------------- 3 weights -> bf16 planes --------------------------------------
__global__ void __launch_bounds__(256) wconv3(
    const float* __restrict__ w_q, const float* __restrict__ w_k,
    const float* __restrict__ w_v, __nv_bfloat16* __restrict__ dst)
{
    int mat = blockIdx.y;
    const float* src = mat == 0 ? w_q : mat == 1 ? w_k : w_v;
    dst += (size_t)mat * PLANE;
    for (int idx = blockIdx.x * 256 + threadIdx.x; idx < PLANE;
         idx += gridDim.x * 256)
        dst[idx] = __float2bfloat16(src[idx]);
}

// ---------------- mma / async helpers -------------------------------------------
__device__ __forceinline__ void mma_bf16(float* c, const uint32_t* a,
                                         const uint32_t* b)
{
    asm volatile(
        "mma.sync.aligned.m16n8k16.row.col.f32.bf16.bf16.f32 "
        "{%0,%1,%2,%3}, {%4,%5,%6,%7}, {%8,%9}, {%0,%1,%2,%3};"
        : "+f"(c[0]), "+f"(c[1]), "+f"(c[2]), "+f"(c[3])
        : "r"(a[0]), "r"(a[1]), "r"(a[2]), "r"(a[3]), "r"(b[0]), "r"(b[1]));
}
__device__ __forceinline__ void ldsm_x4(uint32_t* r, uint32_t addr)
{
    asm volatile("ldmatrix.sync.aligned.m8n8.x4.shared.b16 {%0,%1,%2,%3}, [%4];"
        : "=r"(r[0]), "=r"(r[1]), "=r"(r[2]), "=r"(r[3]) : "r"(addr));
}
__device__ __forceinline__ void ldsm_x2(uint32_t* r, uint32_t addr)
{
    asm volatile("ldmatrix.sync.aligned.m8n8.x2.shared.b16 {%0,%1}, [%2];"
        : "=r"(r[0]), "=r"(r[1]) : "r"(addr));
}
__device__ __forceinline__ void cp_async16(uint32_t dst, const void* src)
{
    asm volatile("cp.async.cg.shared.global [%0], [%1], 16;"
        :: "r"(dst), "l"(src) : "memory");
}
#define CP_COMMIT() asm volatile("cp.async.commit_group;" ::: "memory")
#define CP_WAIT(n)  asm volatile("cp.async.wait_group %0;" :: "n"(n) : "memory")

__device__ __forceinline__ uint32_t pack_bf2(float a, float b) {
    __nv_bfloat162 h = __floats2bfloat162_rn(a, b);
    return *reinterpret_cast<uint32_t*>(&h);
}

// ---------------- shared GEMM body ----------------------------------------------
__device__ __forceinline__ void gemm_body(
    uint32_t* sm, float* sP, float* ssP,
    const void* __restrict__ Xv, int inBf16,
    const __nv_bfloat16* __restrict__ whi, int wStride, int mTiles,
    void* __restrict__ Out0, void* __restrict__ Out1, int outBf16,
    const float* __restrict__ R,
    const float* __restrict__ gw, const float* __restrict__ gb,
    int np0, int b)
{
    uint32_t* Bh = sm;
    int tid  = threadIdx.x;
    int w    = tid >> 5, lane = tid & 31;
    int wm   = w >> 2,  wn = w & 3;
    int g    = lane >> 2, t = lane & 3;
    const __nv_bfloat16* wH = whi + (size_t)b * wStride;
    uint32_t smBase = (uint32_t)__cvta_generic_to_shared(sm);

    {
        int p = tid & 127, kh = tid >> 7;
        if (inBf16) {
            const __nv_bfloat16* xc =
                (const __nv_bfloat16*)Xv + (size_t)b * C_ * HW_ + np0 + p;
            #pragma unroll
            for (int i = 0; i < 48; i++) {
                int kp = kh * 48 + i, k = kp * 2;
                union { __nv_bfloat16 h[2]; uint32_t u; } pk;
                pk.h[0] = xc[(size_t)k * HW_];
                pk.h[1] = xc[(size_t)(k + 1) * HW_];
                Bh[p * 100 + kp] = pk.u;
            }
        } else {
            const float* xc = (const float*)Xv + (size_t)b * C_ * HW_ + np0 + p;
            float s = 0.f, ss = 0.f;
            #pragma unroll
            for (int i = 0; i < 48; i++) {
                int k = kh * 96 + i * 2;
                float x0 = xc[(size_t)k * HW_];
                float x1 = xc[(size_t)(k + 1) * HW_];
                s += x0 + x1;
                ss = fmaf(x0, x0, fmaf(x1, x1, ss));
                Bh[p * 100 + kh * 48 + i] = pack_bf2(x0, x1);
            }
            sP[tid] = s; ssP[tid] = ss;
            __syncthreads();
            float st  = sP[p] + sP[p + 128];
            float sst = ssP[p] + ssP[p + 128];
            float mu_ = st * (1.f / C_);
            float rs_ = rsqrtf(sst * (1.f / C_) - mu_ * mu_ + 1e-5f);
            const float2* gw2 = (const float2*)gw;
            const float2* gb2 = (const float2*)gb;
            #pragma unroll
            for (int i = 0; i < 48; i++) {
                int kp = kh * 48 + i;
                uint32_t u = Bh[p * 100 + kp];
                __nv_bfloat162 hv = *reinterpret_cast<__nv_bfloat162*>(&u);
                float x0 = __bfloat162float(hv.x);
                float x1 = __bfloat162float(hv.y);
                float2 gwp = __ldg(&gw2[kp]);
                float2 gbp = __ldg(&gb2[kp]);
                x0 = (x0 - mu_) * rs_ * gwp.x + gbp.x;
                x1 = (x1 - mu_) * rs_ * gwp.y + gbp.y;
                Bh[p * 100 + kp] = pack_bf2(x0, x1);
            }
        }
    }

    uint32_t baseB[2];
    #pragma unroll
    for (int in2 = 0; in2 < 2; in2++) {
        int row = wn * 32 + in2 * 16 + ((lane >> 4) << 3) + (lane & 7);
        baseB[in2] = smBase + (uint32_t)((row * 100 + ((lane >> 3) & 1) * 4) * 4);
    }

    auto copyA = [&](int mt, int buf) {
        #pragma unroll
        for (int i = 0; i < 6; i++) {
            int idx = tid + 256 * i;
            int row = idx / 24, j = idx % 24;
            size_t go = (size_t)(mt * 64 + row) * C_ + j * 8;
            uint32_t dst = smBase +
                (uint32_t)((12800 + buf * 6400 + row * 100 + j * 4) * 4);
            cp_async16(dst, &wH[go]);
        }
    };

    copyA(0, 0);
    CP_COMMIT();

    for (int mt = 0; mt < mTiles; mt++) {
        int buf = mt & 1;
        if (mt + 1 < mTiles) {
            copyA(mt + 1, buf ^ 1);
            CP_COMMIT();
            CP_WAIT(1);
        } else {
            CP_WAIT(0);
        }
        __syncthreads();

        uint32_t aB = smBase + (uint32_t)((12800 + buf * 6400) * 4);
        uint32_t baseA[2];
        #pragma unroll
        for (int im = 0; im < 2; im++) {
            int row = wm * 32 + im * 16 + (lane & 15);
            baseA[im] = aB + (uint32_t)(row * 400 + (lane >> 4) * 16);
        }

        float acc[8][4];
        #pragma unroll
        for (int i = 0; i < 8; i++)
            #pragma unroll
            for (int j = 0; j < 4; j++) acc[i][j] = 0.f;

        #pragma unroll
        for (int s = 0; s < 12; s++) {
            uint32_t ah[2][4], bh[2][4];
            #pragma unroll
            for (int im = 0; im < 2; im++)
                ldsm_x4(ah[im], baseA[im] + s * 32);
            #pragma unroll
            for (int in2 = 0; in2 < 2; in2++)
                ldsm_x4(bh[in2], baseB[in2] + s * 32);
            #pragma unroll
            for (int im = 0; im < 2; im++)
                #pragma unroll
                for (int in_ = 0; in_ < 4; in_++)
                    mma_bf16(acc[im * 4 + in_], ah[im],
                             &bh[in_ >> 1][(in_ & 1) * 2]);
        }

        #pragma unroll
        for (int im = 0; im < 2; im++) {
            #pragma unroll
            for (int in_ = 0; in_ < 4; in_++) {
                const float* c = acc[im * 4 + in_];
                int grow = mt * 64 + wm * 32 + im * 16 + g;
                int col  = np0 + wn * 32 + in_ * 8 + t * 2;
                #pragma unroll
                for (int half = 0; half < 2; half++) {
                    int rr = grow + half * 8;
                    float2 v = make_float2(c[half * 2], c[half * 2 + 1]);
                    size_t off = (size_t)b * C_ * HW_ +
                        (size_t)((rr < C_) ? rr : rr - C_) * HW_ + col;
                    if (outBf16) {
                        __nv_bfloat16* o = (rr < C_)
                            ? (__nv_bfloat16*)Out0 + off
                            : (__nv_bfloat16*)Out1 + off;
                        *reinterpret_cast<uint32_t*>(o) = pack_bf2(v.x, v.y);
                    } else {
                        float* o = (rr < C_) ? (float*)Out0 + off
                                             : (float*)Out1 + off;
                        if (R && rr < C_) {
                            const float2 r2 = *reinterpret_cast<const float2*>(
                                &R[(size_t)b * C_ * HW_ + (size_t)rr * HW_ + col]);
                            v.x += r2.x; v.y += r2.y;
                        }
                        *reinterpret_cast<float2*>(o) = v;
                    }
                }
            }
        }
        __syncthreads();
    }
}

// ---------------- merged q + kv producer GEMM (long kv job first) ----------------
__global__ void __launch_bounds__(256) mma_gemm_qkv(
    const float* __restrict__ q_in, const float* __restrict__ xx,
    const __nv_bfloat16* __restrict__ whi,
    __nv_bfloat16* __restrict__ qb, __nv_bfloat16* __restrict__ kb,
    __nv_bfloat16* __restrict__ vb,
    const float* __restrict__ gw, const float* __restrict__ gb)
{
    extern __shared__ uint32_t sm[];
    __shared__ float sP[256], ssP[256];
    int np0 = blockIdx.x * 128;
    int b   = blockIdx.y;
    if (blockIdx.z == 0)
        gemm_body(sm, sP, ssP, xx, 0, whi + PLANE, 0, 6, kb, vb, 1,
                  nullptr, gw, gb, np0, b);
    else
        gemm_body(sm, sP, ssP, q_in, 0, whi, 0, 3, qb, qb, 1,
                  nullptr, gw, gb, np0, b);
}

// ---------------- final GEMM ------------------------------------------------------
__global__ void __launch_bounds__(256) mma_gemm_fin(
    const __nv_bfloat16* __restrict__ vd,
    const __nv_bfloat16* __restrict__ whi,
    float* __restrict__ out, const float* __restrict__ q_in)
{
    extern __shared__ uint32_t sm[];
    __shared__ float sP[256], ssP[256];
    gemm_body(sm, sP, ssP, vd, 1, whi, PLANE, 3, out, out, 0,
              q_in, nullptr, nullptr, blockIdx.x * 128, blockIdx.y);
}

// ---------------- depthwise helpers ------------------------------------------------
__device__ __forceinline__ void dw_load_row_bf(
    const __nv_bfloat16* __restrict__ ib, int y, int lane,
    float& l, float4& f, float& r)
{
    if ((unsigned)y < (unsigned)H_) {
        uint2 u = *reinterpret_cast<const uint2*>(ib + (size_t)y * W_ + lane * 4);
        __nv_bfloat162 lo = *reinterpret_cast<__nv_bfloat162*>(&u.x);
        __nv_bfloat162 hi = *reinterpret_cast<__nv_bfloat162*>(&u.y);
        f = make_float4(__bfloat162float(lo.x), __bfloat162float(lo.y),
                        __bfloat162float(hi.x), __bfloat162float(hi.y));
    } else {
        f = make_float4(0.f, 0.f, 0.f, 0.f);
    }
    float lw = __shfl_up_sync(0xffffffffu, f.w, 1);
    float rx = __shfl_down_sync(0xffffffffu, f.x, 1);
    l = (lane == 0)  ? 0.f : lw;
    r = (lane == 31) ? 0.f : rx;
}

__device__ __forceinline__ void dw_plane(
    const __nv_bfloat16* __restrict__ ib, __nv_bfloat16* __restrict__ ob,
    const float* __restrict__ wp)
{
    float w00 = __ldg(wp + 0), w01 = __ldg(wp + 1), w02 = __ldg(wp + 2);
    float w10 = __ldg(wp + 3), w11 = __ldg(wp + 4), w12 = __ldg(wp + 5);
    float w20 = __ldg(wp + 6), w21 = __ldg(wp + 7), w22 = __ldg(wp + 8);

    int warp = threadIdx.x >> 5, lane = threadIdx.x & 31;
    int y0 = warp * 16;

    float pl, pr, cl, cr, nl, nr;
    float4 pf, cf, nf;
    dw_load_row_bf(ib, y0 - 1, lane, pl, pf, pr);
    dw_load_row_bf(ib, y0,     lane, cl, cf, cr);

    #pragma unroll
    for (int r = 0; r < 16; r++) {
        int y = y0 + r;
        dw_load_row_bf(ib, y + 1, lane, nl, nf, nr);
        float4 o;
        o.x = fmaf(pl,   w00, fmaf(pf.x, w01, fmaf(pf.y, w02,
              fmaf(cl,   w10, fmaf(cf.x, w11, fmaf(cf.y, w12,
              fmaf(nl,   w20, fmaf(nf.x, w21, nf.y * w22))))))));
        o.y = fmaf(pf.x, w00, fmaf(pf.y, w01, fmaf(pf.z, w02,
              fmaf(cf.x, w10, fmaf(cf.y, w11, fmaf(cf.z, w12,
              fmaf(nf.x, w20, fmaf(nf.y, w21, nf.z * w22))))))));
        o.z = fmaf(pf.y, w00, fmaf(pf.z, w01, fmaf(pf.w, w02,
              fmaf(cf.y, w10, fmaf(cf.z, w11, fmaf(cf.w, w12,
              fmaf(nf.y, w20, fmaf(nf.z, w21, nf.w * w22))))))));
        o.w = fmaf(pf.z, w00, fmaf(pf.w, w01, fmaf(pr,   w02,
              fmaf(cf.z, w10, fmaf(cf.w, w11, fmaf(cr,   w12,
              fmaf(nf.z, w20, fmaf(nf.w, w21, nr * w22))))))));
        uint2 st;
        st.x = pack_bf2(o.x, o.y);
        st.y = pack_bf2(o.z, o.w);
        *reinterpret_cast<uint2*>(ob + (size_t)y * W_ + lane * 4) = st;
        pl = cl; pr = cr; pf = cf;
        cl = nl; cr = nr; cf = nf;
    }
}

// ---------------- depthwise 3x3 bf16 (q, k) ---------------------------------------
__global__ void __launch_bounds__(256) dw3qk(
    const __nv_bfloat16* __restrict__ inq, const __nv_bfloat16* __restrict__ ink,
    __nv_bfloat16* __restrict__ outq, __nv_bfloat16* __restrict__ outk,
    const float* __restrict__ wq, const float* __restrict__ wk)
{
    int which = blockIdx.y;
    const __nv_bfloat16* in  = which == 0 ? inq  : ink;
    __nv_bfloat16*       out = which == 0 ? outq : outk;
    const float*         wt  = which == 0 ? wq   : wk;
    int bc = blockIdx.x;
    dw_plane(in + (size_t)bc * HW_, out + (size_t)bc * HW_, wt + (bc % C_) * 9);
}

// ---------------- heterogeneous launch: gram (mma) + dw3(v) ----------------------
// blocks [0, 512): gram; blocks [512, 2048): dwconv of v (independent work).
#define GR_STRIDE 36
#define GR_BUFW   (96 * GR_STRIDE)
__global__ void __launch_bounds__(256) gram_dwv(
    const __nv_bfloat16* __restrict__ qd, const __nv_bfloat16* __restrict__ kd,
    float* __restrict__ part,
    const __nv_bfloat16* __restrict__ vb, __nv_bfloat16* __restrict__ vd,
    const float* __restrict__ wv)
{
    __shared__ uint32_t gsm[2][GR_BUFW];
    __shared__ float nqs[96];

    int bid = blockIdx.x;
    if (bid >= 512) {
        // ---- dwconv(v) path ----
        int bc = bid - 512;
        dw_plane(vb + (size_t)bc * HW_, vd + (size_t)bc * HW_,
                 wv + (bc % C_) * 9);
        return;
    }

    // ---- gram path (identical to R16 gram_mma) ----
    int chunk = bid & 15;
    int bh    = bid >> 4;
    int b = bh >> 2, h = bh & 3;
    size_t base = ((size_t)b * C_ + h * DH) * HW_ + (size_t)chunk * 1024;
    const __nv_bfloat16* qb_ = qd + base;
    const __nv_bfloat16* kb_ = kd + base;

    int tid = threadIdx.x;
    int w = tid >> 5, lane = tid & 31;
    int wm = w >> 1, wn = w & 1;
    int g = lane >> 2, t4 = lane & 3;
    uint32_t smBase = (uint32_t)__cvta_generic_to_shared(gsm);

    if (tid < 96) nqs[tid] = 0.f;

    int rowi[3], segi[3];
    #pragma unroll
    for (int it = 0; it < 3; it++) {
        int idx = tid + 256 * it;
        rowi[it] = idx >> 3;
        segi[it] = idx & 7;
    }
    float naccA[3] = {0.f, 0.f, 0.f};
    float naccB[3] = {0.f, 0.f, 0.f};

    uint32_t offA = 0, offB4 = 0, offB2 = 0;
    if (w < 6) {
        int rA = wm * 16 + (lane & 15);
        offA = (uint32_t)((rA * GR_STRIDE + (lane >> 4) * 4) * 4);
        int rB4 = 48 + wn * 24 + ((lane >> 4) << 3) + (lane & 7);
        offB4 = (uint32_t)((rB4 * GR_STRIDE + ((lane >> 3) & 1) * 4) * 4);
        int l15 = lane & 15;
        int rB2 = 48 + wn * 24 + 16 + (l15 & 7);
        offB2 = (uint32_t)((rB2 * GR_STRIDE + ((l15 >> 3) & 1) * 4) * 4);
    }

    float acc[3][4];
    #pragma unroll
    for (int i = 0; i < 3; i++)
        #pragma unroll
        for (int j = 0; j < 4; j++) acc[i][j] = 0.f;

    uint4 rg[3];
    auto loadTile = [&](int t) {
        #pragma unroll
        for (int it = 0; it < 3; it++) {
            const __nv_bfloat16* src = (rowi[it] < 48)
                ? qb_ + (size_t)rowi[it] * HW_
                : kb_ + (size_t)(rowi[it] - 48) * HW_;
            rg[it] = *reinterpret_cast<const uint4*>(src + t * 64 + segi[it] * 8);
            const uint32_t* u = &rg[it].x;
            __nv_bfloat162 h0 = *reinterpret_cast<const __nv_bfloat162*>(&u[0]);
            __nv_bfloat162 h1 = *reinterpret_cast<const __nv_bfloat162*>(&u[1]);
            __nv_bfloat162 h2 = *reinterpret_cast<const __nv_bfloat162*>(&u[2]);
            __nv_bfloat162 h3 = *reinterpret_cast<const __nv_bfloat162*>(&u[3]);
            float a0 = __bfloat162float(h0.x), a1 = __bfloat162float(h0.y);
            float a2 = __bfloat162float(h1.x), a3 = __bfloat162float(h1.y);
            float b0 = __bfloat162float(h2.x), b1 = __bfloat162float(h2.y);
            float b2 = __bfloat162float(h3.x), b3 = __bfloat162float(h3.y);
            naccA[it] = fmaf(a0, a0, fmaf(a1, a1,
                        fmaf(a2, a2, fmaf(a3, a3, naccA[it]))));
            naccB[it] = fmaf(b0, b0, fmaf(b1, b1,
                        fmaf(b2, b2, fmaf(b3, b3, naccB[it]))));
        }
    };
    auto storeTile = [&](int buf) {
        #pragma unroll
        for (int it = 0; it < 3; it++) {
            uint32_t* d = &gsm[buf][rowi[it] * GR_STRIDE + segi[it] * 4];
            d[0] = rg[it].x; d[1] = rg[it].y; d[2] = rg[it].z; d[3] = rg[it].w;
        }
    };

    loadTile(0);
    storeTile(0);

    for (int t = 0; t < 16; t++) {
        __syncthreads();
        if (t < 15) loadTile(t + 1);
        if (w < 6) {
            uint32_t bufOff = smBase + (uint32_t)((t & 1) * GR_BUFW * 4);
            #pragma unroll
            for (int s = 0; s < 4; s++) {
                uint32_t a[4], b4[4], b2[2];
                ldsm_x4(a,  bufOff + offA  + s * 32);
                ldsm_x4(b4, bufOff + offB4 + s * 32);
                ldsm_x2(b2, bufOff + offB2 + s * 32);
                mma_bf16(acc[0], a, &b4[0]);
                mma_bf16(acc[1], a, &b4[2]);
                mma_bf16(acc[2], a, b2);
            }
        }
        if (t < 15) {
            __syncthreads();
            storeTile((t + 1) & 1);
        }
    }

    #pragma unroll
    for (int it = 0; it < 3; it++)
        atomicAdd(&nqs[rowi[it]], naccA[it] + naccB[it]);
    __syncthreads();

    float* pb = part + ((size_t)bh * 16 + chunk) * 2400;
    if (w < 6) {
        int i0 = wm * 16;
        #pragma unroll
        for (int f = 0; f < 3; f++) {
            int n0 = wn * 24 + f * 8;
            pb[(i0 + g) * DH + n0 + t4 * 2]     = acc[f][0];
            pb[(i0 + g) * DH + n0 + t4 * 2 + 1] = acc[f][1];
            pb[(i0 + g + 8) * DH + n0 + t4 * 2]     = acc[f][2];
            pb[(i0 + g + 8) * DH + n0 + t4 * 2 + 1] = acc[f][3];
        }
    }
    if (tid < 96) pb[2304 + tid] = nqs[tid];
}

// ---------------- fused: reduce + softmax + build M (o-split, bf16 out) ----------
__global__ void __launch_bounds__(256) softmax_build(
    const float* __restrict__ part, const float* __restrict__ temp,
    const float* __restrict__ wp, __nv_bfloat16* __restrict__ M)
{
    int b = blockIdx.x;
    int oc = blockIdx.y;
    __shared__ float sA[HEADS][DH * DH];
    __shared__ float nq[DH], nk[DH];
    int tid = threadIdx.x;

    for (int h = 0; h < HEADS; h++) {
        int bh = b * HEADS + h;
        for (int e = tid; e < 2400; e += 256) {
            float s = 0.f;
            #pragma unroll
            for (int c = 0; c < 16; c++)
                s += part[((size_t)bh * 16 + c) * 2400 + e];
            if (e < 2304)      sA[h][e] = s;
            else if (e < 2352) nq[e - 2304] = fmaxf(sqrtf(s), 1e-12f);
            else               nk[e - 2352] = fmaxf(sqrtf(s), 1e-12f);
        }
        __syncthreads();
        if (tid < DH) {
            int i = tid;
            float sc = __ldg(&temp[h]) / nq[i];
            float m = -1e30f;
            #pragma unroll 4
            for (int j = 0; j < DH; j++) {
                float s = sA[h][i * DH + j] * sc / nk[j];
                sA[h][i * DH + j] = s;
                m = fmaxf(m, s);
            }
            float sum = 0.f;
            #pragma unroll 4
            for (int j = 0; j < DH; j++) {
                float e = __expf(sA[h][i * DH + j] - m);
                sA[h][i * DH + j] = e;
                sum += e;
            }
            float rs = 1.f / sum;
            #pragma unroll 4
            for (int j = 0; j < DH; j++)
                sA[h][i * DH + j] *= rs;
        }
        __syncthreads();
    }

    for (int e = tid; e < 32 * C_; e += 256) {
        int o = oc * 32 + e / C_, cp = e % C_;
        int h = cp / DH, d = cp % DH;
        const float* wrow = wp + (size_t)o * C_ + h * DH;
        const float* arow = &sA[h][d];
        float s = 0.f;
        #pragma unroll
        for (int i = 0; i < DH; i++)
            s = fmaf(__ldg(&wrow[i]), arow[i * DH], s);
        M[(size_t)b * PLANE + (size_t)o * C_ + cp] = __float2bfloat16(s);
    }
}

// ---------------- launch --------------------------------------------------------
#define GEMM_SMEM 102400

extern "C" void kernel_launch(void* const* d_in, const int* in_sizes, int n_in,
                              void* d_out, int out_size)
{
    const float* xx     = (const float*)d_in[0];
    const float* q_in   = (const float*)d_in[1];
    const float* ln_w   = (const float*)d_in[2];
    const float* ln_b   = (const float*)d_in[3];
    const float* w_q    = (const float*)d_in[4];
    const float* w_k    = (const float*)d_in[5];
    const float* w_v    = (const float*)d_in[6];
    const float* wd_q   = (const float*)d_in[7];
    const float* wd_k   = (const float*)d_in[8];
    const float* wd_v   = (const float*)d_in[9];
    const float* w_proj = (const float*)d_in[10];
    const float* temp   = (const float*)d_in[11];
    float* out = (float*)d_out;

    float* S = nullptr;
    cudaGetSymbolAddress((void**)&S, g_scratch);
    __nv_bfloat16* qb = (__nv_bfloat16*)(S + OFF_QB);
    __nv_bfloat16* kb = (__nv_bfloat16*)(S + OFF_KB);
    __nv_bfloat16* vb = (__nv_bfloat16*)(S + OFF_VB);
    __nv_bfloat16* qd = (__nv_bfloat16*)(S + OFF_QD);
    __nv_bfloat16* kd = (__nv_bfloat16*)(S + OFF_KD);
    __nv_bfloat16* vd = (__nv_bfloat16*)(S + OFF_VD);
    float* part = S + OFF_PART;
    __nv_bfloat16* whi = (__nv_bfloat16*)(S + OFF_WHI);

    cudaFuncSetAttribute(mma_gemm_qkv,
                         cudaFuncAttributeMaxDynamicSharedMemorySize, GEMM_SMEM);
    cudaFuncSetAttribute(mma_gemm_fin,
                         cudaFuncAttributeMaxDynamicSharedMemorySize, GEMM_SMEM);

    // 1. weights -> bf16 planes (slots 0..2)
    wconv3<<<dim3(36, 3), 256>>>(w_q, w_k, w_v, whi);

    // 2. q + kv GEMMs in one launch (z=0: long kv job first)
    mma_gemm_qkv<<<dim3(HW_ / 128, B_, 2), 256, GEMM_SMEM>>>(
        q_in, xx, whi, qb, kb, vb, ln_w, ln_b);

    // 3. depthwise 3x3 for q, k only
    dw3qk<<<dim3(B_ * C_, 2), 256>>>(qb, kb, qd, kd, wd_q, wd_k);

    // 4. heterogeneous: gram (tensor cores) + dwconv(v) in one launch
    gram_dwv<<<512 + B_ * C_, 256>>>(qd, kd, part, vb, vd, wd_v);

    // 5. fused reduce + softmax + M build, o-split
    softmax_build<<<dim3(8, 6), 256>>>(part, temp, w_proj, whi + 3 * PLANE);

    // 6. final GEMM fp32 + residual
    mma_gemm_fin<<<dim3(HW_ / 128, B_), 256, GEMM_SMEM>>>(
        vd, whi + 3 * PLANE, out, q_in);
}